// round 4
// baseline (speedup 1.0000x reference)
#include <cuda_runtime.h>
#include <cuda_bf16.h>

// Problem constants
#define Hd   256
#define Ld   512
#define Bq   8
#define NTOK 4096            // B*L
#define Vv   32000
#define CEMA 0.05f           // 1 - alpha
#define NCH  16              // chunks (processing blocks) per batch
#define NPAIR 136            // NCH*(NCH+1)/2 lower block-pairs

// Scratch (device globals)
__device__ float g_t1[NTOK * 512];
__device__ float g_x [NTOK * Hd];
__device__ float g_he[NTOK * Hd];
__device__ float g_in[NTOK];
__device__ float g_D [Bq * NCH * NCH * 1024];  // D[h][g] blocks; diag = T
__device__ float g_b [Bq * Ld];                // rhs vector (512, last entry unused)
__device__ float g_m [Bq * Hd];
__device__ float g_mm[Bq * Hd];

// ---------------------------------------------------------------------------
// Tiled SGEMM (unchanged)
// ---------------------------------------------------------------------------
template<bool GATHER, bool RELU, bool RESID>
__global__ __launch_bounds__(256) void sgemm_kernel(
    const float* __restrict__ A, const float* __restrict__ Bm,
    const float* __restrict__ bias, float* __restrict__ C,
    int M, int N, int K,
    const int* __restrict__ seq, const float* __restrict__ embed)
{
    constexpr int BM = 64, BN = 64, BK = 16, TM = 4, TN = 4;
    __shared__ float As[BK][BM];
    __shared__ float Bs[BK][BN];

    const int tid = threadIdx.x;
    const int tx = tid % (BN / TN);
    const int ty = tid / (BN / TN);
    const int rowBase = blockIdx.y * BM;
    const int colBase = blockIdx.x * BN;

    float acc[TM][TN];
    #pragma unroll
    for (int i = 0; i < TM; i++)
        #pragma unroll
        for (int j = 0; j < TN; j++) acc[i][j] = 0.f;

    for (int k0 = 0; k0 < K; k0 += BK) {
        #pragma unroll
        for (int i = tid; i < BM * BK; i += 256) {
            int m = i / BK, kk = i % BK;
            int gr = rowBase + m;
            const float* arow = GATHER ? (embed + (long)seq[gr] * K)
                                       : (A + (long)gr * K);
            As[kk][m] = arow[k0 + kk];
        }
        #pragma unroll
        for (int i = tid; i < BK * BN; i += 256) {
            int kk = i / BN, n = i % BN;
            Bs[kk][n] = Bm[(long)(k0 + kk) * N + colBase + n];
        }
        __syncthreads();

        #pragma unroll
        for (int kk = 0; kk < BK; kk++) {
            float af[TM], bf[TN];
            #pragma unroll
            for (int i = 0; i < TM; i++) af[i] = As[kk][ty * TM + i];
            #pragma unroll
            for (int j = 0; j < TN; j++) bf[j] = Bs[kk][tx * TN + j];
            #pragma unroll
            for (int i = 0; i < TM; i++)
                #pragma unroll
                for (int j = 0; j < TN; j++) acc[i][j] += af[i] * bf[j];
        }
        __syncthreads();
    }

    #pragma unroll
    for (int i = 0; i < TM; i++) {
        int r = rowBase + ty * TM + i;
        const float* erow = RESID ? (embed + (long)seq[r] * N) : nullptr;
        #pragma unroll
        for (int j = 0; j < TN; j++) {
            int c = colBase + tx * TN + j;
            float v = acc[i][j] + bias[c];
            if (RELU)  v = fmaxf(v, 0.f);
            if (RESID) v += erow[c];
            C[(long)r * N + c] = v;
        }
    }
}

// ---------------------------------------------------------------------------
// LayerNorm + row norm (unchanged)
// ---------------------------------------------------------------------------
__global__ __launch_bounds__(256) void ln_kernel(
    const float* __restrict__ X, const float* __restrict__ g,
    const float* __restrict__ b, float* __restrict__ Y,
    float* __restrict__ invn)
{
    int row  = blockIdx.x * 8 + (threadIdx.x >> 5);
    int lane = threadIdx.x & 31;
    const float* x = X + (long)row * Hd;

    float v[8];
    float s = 0.f;
    #pragma unroll
    for (int j = 0; j < 8; j++) { v[j] = x[lane + 32 * j]; s += v[j]; }
    #pragma unroll
    for (int o = 16; o > 0; o >>= 1) s += __shfl_xor_sync(0xffffffff, s, o);
    float mu = s * (1.f / Hd);

    float ss = 0.f;
    #pragma unroll
    for (int j = 0; j < 8; j++) { float d = v[j] - mu; ss += d * d; }
    #pragma unroll
    for (int o = 16; o > 0; o >>= 1) ss += __shfl_xor_sync(0xffffffff, ss, o);
    float rstd = rsqrtf(ss * (1.f / Hd) + 1e-5f);

    float ns = 0.f;
    #pragma unroll
    for (int j = 0; j < 8; j++) {
        int c = lane + 32 * j;
        float o = (v[j] - mu) * rstd * g[c] + b[c];
        Y[(long)row * Hd + c] = o;
        ns += o * o;
    }
    #pragma unroll
    for (int o = 16; o > 0; o >>= 1) ns += __shfl_xor_sync(0xffffffff, ns, o);

    if (lane == 0) invn[row] = 1.f / fmaxf(sqrtf(ns), 1e-12f);
}

// ---------------------------------------------------------------------------
// Gram pairs kernel. Block = (batch, pair (h,g) with h<=g).
// Chunk g row j <-> time t = tHi(g)-j, tHi = min(32g+31,510).
// Off-diag: D[h][g][j][jp] = iv(h,j)*iv(g,jp)*(k_{t(h,j)} . k_{t(g,jp)})
// Diag:     T_g = (I + strict_lower(CEMA * D[g][g]))^-1
// ---------------------------------------------------------------------------
__global__ __launch_bounds__(256) void gram_kernel(
    const float* __restrict__ He, const float* __restrict__ invn,
    float* __restrict__ D)
{
    extern __shared__ float sh[];
    float* Kh  = sh;                 // [32][257]
    float* Kg  = Kh + 32 * 257;      // [32][257]
    float* ivh = Kg + 32 * 257;      // [32]
    float* ivg = ivh + 32;           // [32]
    float* G   = ivg + 32;           // [32][33] diag only

    int bId = blockIdx.x / NPAIR;
    int p   = blockIdx.x % NPAIR;
    int h = 0, rem = p;
    while (rem >= NCH - h) { rem -= NCH - h; h++; }
    int g = h + rem;

    int tid = threadIdx.x;
    const float* Hb = He + (long)bId * Ld * Hd;
    const float* In = invn + bId * Ld;
    int tHh = (h == 15) ? 510 : (32 * h + 31);
    int tHg = (g == 15) ? 510 : (32 * g + 31);

    for (int idx = tid; idx < 32 * 256; idx += 256) {
        int j = idx >> 8, c = idx & 255;
        Kh[j * 257 + c] = Hb[(long)(tHh - j) * Hd + c];
    }
    if (tid < 32) ivh[tid] = In[tHh - tid];
    const float* Kg_p = Kh;
    const float* ivg_p = ivh;
    if (g != h) {
        for (int idx = tid; idx < 32 * 256; idx += 256) {
            int j = idx >> 8, c = idx & 255;
            Kg[j * 257 + c] = Hb[(long)(tHg - j) * Hd + c];
        }
        if (tid < 32) ivg[tid] = In[tHg - tid];
        Kg_p = Kg; ivg_p = ivg;
    }
    __syncthreads();

    int ty = tid >> 4, tx = tid & 15;    // 16x16 threads, 2x2 microtile
    float acc[2][2] = {{0.f, 0.f}, {0.f, 0.f}};

    #pragma unroll 4
    for (int kk = 0; kk < 256; kk++) {
        float a0 = Kh[(2 * ty)     * 257 + kk];
        float a1 = Kh[(2 * ty + 1) * 257 + kk];
        float b0 = Kg_p[(2 * tx)     * 257 + kk];
        float b1 = Kg_p[(2 * tx + 1) * 257 + kk];
        acc[0][0] += a0 * b0; acc[0][1] += a0 * b1;
        acc[1][0] += a1 * b0; acc[1][1] += a1 * b1;
    }

    float* Dblk = D + (((long)bId * NCH + h) * NCH + g) * 1024;

    if (h != g) {
        #pragma unroll
        for (int i = 0; i < 2; i++)
            #pragma unroll
            for (int jj = 0; jj < 2; jj++) {
                int r = 2 * ty + i, c = 2 * tx + jj;
                Dblk[r * 32 + c] = ivh[r] * ivg_p[c] * acc[i][jj];
            }
    } else {
        #pragma unroll
        for (int i = 0; i < 2; i++)
            #pragma unroll
            for (int jj = 0; jj < 2; jj++) {
                int r = 2 * ty + i, c = 2 * tx + jj;
                G[r * 33 + c] = CEMA * ivh[r] * ivh[c] * acc[i][jj];
            }
        __syncthreads();
        // warp 0: T = (I + strict_lower(G))^-1, per-column fwd substitution
        if (tid < 32) {
            int c = tid;
            float x[32];
            #pragma unroll
            for (int j = 0; j < 32; j++) {
                float sum = (j == c) ? 1.f : 0.f;
                #pragma unroll
                for (int l = 0; l < 32; l++)
                    if (l < j) sum -= G[j * 33 + l] * x[l];
                x[j] = sum;
            }
            #pragma unroll
            for (int j = 0; j < 32; j++)
                Dblk[j * 32 + c] = x[j];
        }
    }
}

// ---------------------------------------------------------------------------
// bvec: b[(g,j)] = iv(g,j) * (k_{t(g,j)} . q),  q = He row 511 per batch
// grid = 8*16 blocks, 256 threads (8 warps x 4 rows)
// ---------------------------------------------------------------------------
__global__ __launch_bounds__(256) void bvec_kernel(
    const float* __restrict__ He, const float* __restrict__ invn,
    float* __restrict__ bvec)
{
    __shared__ float q[256];
    int bId = blockIdx.x >> 4;
    int g   = blockIdx.x & 15;
    int tid = threadIdx.x;
    int w = tid >> 5, lane = tid & 31;
    const float* Hb = He + (long)bId * Ld * Hd;
    q[tid] = Hb[511 * Hd + tid];
    __syncthreads();

    int tHi = (g == 15) ? 510 : (32 * g + 31);
    #pragma unroll
    for (int jj = 0; jj < 4; jj++) {
        int j = w * 4 + jj;
        int t = tHi - j;
        float s = 0.f;
        #pragma unroll
        for (int e = 0; e < 8; e++)
            s += Hb[(long)t * Hd + lane + 32 * e] * q[lane + 32 * e];
        #pragma unroll
        for (int o = 16; o > 0; o >>= 1)
            s += __shfl_xor_sync(0xffffffff, s, o);
        if (lane == 0) {
            float val = s * invn[bId * Ld + t];
            if (g == 15 && j == 31) val = 0.f;
            bvec[bId * Ld + g * 32 + j] = val;
        }
    }
}

// ---------------------------------------------------------------------------
// Block forward substitution + readout. One block per batch, 256 threads.
// for g = 15..0:  s_g = T_g * b_g;  cs_g = CEMA*s_g;
//                 b_h -= D[h][g] * cs_g  for all h<g (parallel)
// m = sum_i cs_i * k_i
// ---------------------------------------------------------------------------
__global__ __launch_bounds__(256) void solve_kernel(
    const float* __restrict__ He, const float* __restrict__ D,
    const float* __restrict__ bvec, float* __restrict__ mout)
{
    extern __shared__ float sh[];
    float* T  = sh;              // [16][32*33]
    float* bv = T + 16 * 1056;   // [512]
    float* cs = bv + 512;        // [512]

    int bId = blockIdx.x;
    int tid = threadIdx.x;
    const float* Db = D + (long)bId * NCH * NCH * 1024;

    // load all diagonal inverses (padded stride 33)
    for (int g = 0; g < 16; g++) {
        const float* Tg = Db + (g * NCH + g) * 1024;
        #pragma unroll
        for (int e = tid; e < 1024; e += 256)
            T[g * 1056 + (e >> 5) * 33 + (e & 31)] = Tg[e];
    }
    bv[tid]       = bvec[bId * Ld + tid];
    bv[256 + tid] = bvec[bId * Ld + 256 + tid];
    __syncthreads();

    int jrow = tid >> 3, sub = tid & 7;
    for (int g = 15; g >= 0; --g) {
        // s_g = T_g * r  (32x32 matvec across 256 threads)
        {
            const float* Tg = T + g * 1056 + jrow * 33;
            const float* r  = bv + g * 32;
            float t = 0.f;
            #pragma unroll
            for (int q = 0; q < 4; q++)
                t += Tg[sub * 4 + q] * r[sub * 4 + q];
            t += __shfl_xor_sync(0xffffffff, t, 1);
            t += __shfl_xor_sync(0xffffffff, t, 2);
            t += __shfl_xor_sync(0xffffffff, t, 4);
            if (sub == 0) {
                bool ok = (g < 15) || (jrow < 31);
                cs[g * 32 + jrow] = ok ? CEMA * t : 0.f;
            }
        }
        __syncthreads();

        // parallel rank update of all later-time (h<g) rhs blocks
        if (g > 0) {
            const float* csg = cs + g * 32;
            for (int r2 = tid; r2 < 32 * g; r2 += 256) {
                int h = r2 >> 5, j = r2 & 31;
                const float4* Drow = (const float4*)
                    (Db + ((long)(h * NCH + g) << 10) + (j << 5));
                float acc = 0.f;
                #pragma unroll
                for (int q = 0; q < 8; q++) {
                    float4 d = Drow[q];
                    acc += d.x * csg[q * 4]     + d.y * csg[q * 4 + 1]
                         + d.z * csg[q * 4 + 2] + d.w * csg[q * 4 + 3];
                }
                bv[h * 32 + j] -= acc;
            }
            __syncthreads();
        }
    }

    // m[c] = sum_{g,j} cs[g*32+j] * He[t(g,j)][c]   (coalesced streams)
    float m = 0.f;
    const float* Hb = He + (long)bId * Ld * Hd;
    for (int g = 15; g >= 0; --g) {
        int tHi = (g == 15) ? 510 : (32 * g + 31);
        #pragma unroll 4
        for (int j = 0; j < 32; j++)
            m += cs[g * 32 + j] * Hb[(long)(tHi - j) * Hd + tid];
    }
    mout[bId * Hd + tid] = m;
}

// ---------------------------------------------------------------------------
// mm = m @ Wrp + brp
// ---------------------------------------------------------------------------
__global__ __launch_bounds__(256) void rp_kernel(
    const float* __restrict__ m, const float* __restrict__ Wrp,
    const float* __restrict__ brp, float* __restrict__ mm)
{
    int b = blockIdx.x, c = threadIdx.x;
    __shared__ float ms[Hd];
    ms[c] = m[b * Hd + c];
    __syncthreads();
    float acc = brp[c];
    #pragma unroll 8
    for (int k = 0; k < Hd; k++) acc += ms[k] * Wrp[k * Hd + c];
    mm[b * Hd + c] = acc;
}

// ---------------------------------------------------------------------------
// out[8,32000] = mm @ Wout + bout
// ---------------------------------------------------------------------------
__global__ __launch_bounds__(128) void out_kernel(
    const float* __restrict__ mm, const float* __restrict__ Wout,
    const float* __restrict__ bout, float* __restrict__ out)
{
    __shared__ float ms[Bq][Hd];
    int tid = threadIdx.x;
    #pragma unroll
    for (int i = tid; i < Bq * Hd; i += 128) ms[i >> 8][i & 255] = mm[i];
    __syncthreads();

    int col = blockIdx.x * 128 + tid;
    float acc[Bq];
    float bo = bout[col];
    #pragma unroll
    for (int b = 0; b < Bq; b++) acc[b] = bo;

    #pragma unroll 4
    for (int k = 0; k < Hd; k++) {
        float w = Wout[(long)k * Vv + col];
        #pragma unroll
        for (int b = 0; b < Bq; b++) acc[b] += ms[b][k] * w;
    }
    #pragma unroll
    for (int b = 0; b < Bq; b++) out[(long)b * Vv + col] = acc[b];
}

// ---------------------------------------------------------------------------
extern "C" void kernel_launch(void* const* d_in, const int* in_sizes, int n_in,
                              void* d_out, int out_size)
{
    const int*   seq   = (const int*)  d_in[0];
    const float* embed = (const float*)d_in[1];
    const float* W1    = (const float*)d_in[2];
    const float* b1    = (const float*)d_in[3];
    const float* W2    = (const float*)d_in[4];
    const float* b2    = (const float*)d_in[5];
    const float* gamma = (const float*)d_in[6];
    const float* beta  = (const float*)d_in[7];
    const float* Wrp   = (const float*)d_in[8];
    const float* brp   = (const float*)d_in[9];
    const float* Wout  = (const float*)d_in[10];
    const float* bout  = (const float*)d_in[11];
    float* out = (float*)d_out;

    float *t1, *x, *he, *invn, *Dm, *bv, *m, *mm;
    cudaGetSymbolAddress((void**)&t1,   g_t1);
    cudaGetSymbolAddress((void**)&x,    g_x);
    cudaGetSymbolAddress((void**)&he,   g_he);
    cudaGetSymbolAddress((void**)&invn, g_in);
    cudaGetSymbolAddress((void**)&Dm,   g_D);
    cudaGetSymbolAddress((void**)&bv,   g_b);
    cudaGetSymbolAddress((void**)&m,    g_m);
    cudaGetSymbolAddress((void**)&mm,   g_mm);

    const int gramSmem  = (2 * 32 * 257 + 64 + 32 * 33) * 4;  // 70272
    const int solveSmem = (16 * 1056 + 512 + 512) * 4;        // 71680
    cudaFuncSetAttribute(gram_kernel,
        cudaFuncAttributeMaxDynamicSharedMemorySize, gramSmem);
    cudaFuncSetAttribute(solve_kernel,
        cudaFuncAttributeMaxDynamicSharedMemorySize, solveSmem);

    // 1) t1 = relu(embed[seq] @ W1 + b1)
    sgemm_kernel<true, true, false><<<dim3(512 / 64, 4096 / 64), 256>>>(
        nullptr, W1, b1, t1, NTOK, 512, Hd, seq, embed);

    // 2) x = t1 @ W2 + b2 + embed[seq]
    sgemm_kernel<false, false, true><<<dim3(Hd / 64, 4096 / 64), 256>>>(
        t1, W2, b2, x, NTOK, Hd, 512, seq, embed);

    // 3) LayerNorm + row norms
    ln_kernel<<<NTOK / 8, 256>>>(x, gamma, beta, he, invn);

    // 4a) all Gram blocks + diagonal inverses (fully parallel, 1088 blocks)
    gram_kernel<<<Bq * NPAIR, 256, gramSmem>>>(he, invn, Dm);

    // 4b) rhs b = iv .* (K q) (parallel, 128 blocks)
    bvec_kernel<<<Bq * NCH, 256>>>(he, invn, bv);

    // 4c) block forward substitution + readout m (8 blocks, 16 tiny steps)
    solve_kernel<<<Bq, 256, solveSmem>>>(he, Dm, bv, m);

    // 5) mm = m @ Wrp + brp
    rp_kernel<<<Bq, Hd>>>(m, Wrp, brp, mm);

    // 6) out = mm @ Wout + bout
    out_kernel<<<Vv / 128, 128>>>(mm, Wout, bout, out);
}

// round 5
// speedup vs baseline: 1.5948x; 1.5948x over previous
#include <cuda_runtime.h>
#include <cuda_bf16.h>

// Problem constants
#define Hd   256
#define Ld   512
#define Bq   8
#define NTOK 4096            // B*L
#define Vv   32000
#define CEMA 0.05f           // 1 - alpha
#define CSZ  64              // chunk size
#define NCH  8               // chunks per batch
#define KSTR 260             // K-tile smem row stride (scan)
#define PSTR 265             // K-tile smem row stride (prep)
#define TSTR 68              // T smem row stride (16B-aligned)

// Scratch (device globals)
__device__ float g_t1[NTOK * 512];
__device__ float g_x [NTOK * Hd];
__device__ float g_he[NTOK * Hd];
__device__ float g_in[NTOK];
__device__ float g_T [Bq * NCH * CSZ * CSZ];  // per-chunk (I+cL)^-1
__device__ float g_m [Bq * Hd];
__device__ float g_mm[Bq * Hd];

// cp.async helpers
__device__ __forceinline__ void cp16(void* dst, const void* src) {
    unsigned d = (unsigned)__cvta_generic_to_shared(dst);
    asm volatile("cp.async.ca.shared.global [%0], [%1], 16;\n" :: "r"(d), "l"(src));
}
#define CP_COMMIT() asm volatile("cp.async.commit_group;\n" ::: "memory")
#define CP_WAIT0()  asm volatile("cp.async.wait_group 0;\n" ::: "memory")

// ---------------------------------------------------------------------------
// SGEMM v2: BM=128, BN=64, BK=16, 128 threads, 8x8 microtile.
// 16 smem words per 64 FMA -> crossbar-saturating at 128 FMA/cyc/SM.
// Double-buffered smem with register-staged global loads.
// ---------------------------------------------------------------------------
template<bool GATHER, bool RELU, bool RESID>
__global__ __launch_bounds__(128) void sgemm_kernel(
    const float* __restrict__ A, const float* __restrict__ Bm,
    const float* __restrict__ bias, float* __restrict__ C,
    int M, int N, int K,
    const int* __restrict__ seq, const float* __restrict__ embed)
{
    constexpr int BM = 128, BN = 64, BK = 16;
    __shared__ float As[2][BK][BM];
    __shared__ float Bs[2][BK][72];

    const int tid = threadIdx.x;
    const int tx = tid & 7;          // 8 col-groups
    const int ty = tid >> 3;         // 16 row-groups
    const int rowBase = blockIdx.y * BM;
    const int colBase = blockIdx.x * BN;

    // A: thread owns global row rowBase+tid
    const float* arow;
    if (GATHER) arow = embed + (long)seq[rowBase + tid] * K;
    else        arow = A + (long)(rowBase + tid) * K;
    // B: thread loads row br, 8 cols at bc
    const int br = tid >> 3, bc = (tid & 7) * 8;

    float4 aN[4], bN[2];
    // k0 = 0 tile
    #pragma unroll
    for (int q = 0; q < 4; q++) aN[q] = *(const float4*)(arow + q * 4);
    bN[0] = *(const float4*)(Bm + (long)br * N + colBase + bc);
    bN[1] = *(const float4*)(Bm + (long)br * N + colBase + bc + 4);
    {
        const float* af = (const float*)aN;
        #pragma unroll
        for (int kk = 0; kk < BK; kk++) As[0][kk][tid] = af[kk];
        *(float4*)&Bs[0][br][bc]     = bN[0];
        *(float4*)&Bs[0][br][bc + 4] = bN[1];
    }
    __syncthreads();

    float acc[8][8];
    #pragma unroll
    for (int i = 0; i < 8; i++)
        #pragma unroll
        for (int j = 0; j < 8; j++) acc[i][j] = 0.f;

    const int niter = K / BK;
    for (int it = 0; it < niter; it++) {
        const int cur = it & 1;
        if (it + 1 < niter) {
            const int k0 = (it + 1) * BK;
            #pragma unroll
            for (int q = 0; q < 4; q++)
                aN[q] = *(const float4*)(arow + k0 + q * 4);
            bN[0] = *(const float4*)(Bm + (long)(k0 + br) * N + colBase + bc);
            bN[1] = *(const float4*)(Bm + (long)(k0 + br) * N + colBase + bc + 4);
        }

        #pragma unroll
        for (int kk = 0; kk < BK; kk++) {
            float af[8], bf[8];
            *(float4*)&af[0] = *(const float4*)&As[cur][kk][ty * 8];
            *(float4*)&af[4] = *(const float4*)&As[cur][kk][ty * 8 + 4];
            *(float4*)&bf[0] = *(const float4*)&Bs[cur][kk][tx * 8];
            *(float4*)&bf[4] = *(const float4*)&Bs[cur][kk][tx * 8 + 4];
            #pragma unroll
            for (int i = 0; i < 8; i++)
                #pragma unroll
                for (int j = 0; j < 8; j++)
                    acc[i][j] += af[i] * bf[j];
        }

        if (it + 1 < niter) {
            const int nb = (it + 1) & 1;
            const float* af = (const float*)aN;
            #pragma unroll
            for (int kk = 0; kk < BK; kk++) As[nb][kk][tid] = af[kk];
            *(float4*)&Bs[nb][br][bc]     = bN[0];
            *(float4*)&Bs[nb][br][bc + 4] = bN[1];
        }
        __syncthreads();
    }

    // epilogue
    float bia[8];
    *(float4*)&bia[0] = *(const float4*)(bias + colBase + tx * 8);
    *(float4*)&bia[4] = *(const float4*)(bias + colBase + tx * 8 + 4);

    #pragma unroll
    for (int i = 0; i < 8; i++) {
        const int r = rowBase + ty * 8 + i;
        float res[8];
        if (RESID) {
            const float* erow = embed + (long)seq[r] * N + colBase + tx * 8;
            *(float4*)&res[0] = *(const float4*)(erow);
            *(float4*)&res[4] = *(const float4*)(erow + 4);
        }
        float o[8];
        #pragma unroll
        for (int j = 0; j < 8; j++) {
            float v = acc[i][j] + bia[j];
            if (RELU)  v = fmaxf(v, 0.f);
            if (RESID) v += res[j];
            o[j] = v;
        }
        float* crow = C + (long)r * N + colBase + tx * 8;
        *(float4*)(crow)     = *(float4*)&o[0];
        *(float4*)(crow + 4) = *(float4*)&o[4];
    }
}

// ---------------------------------------------------------------------------
// Prep kernel: per 64-chunk: LayerNorm rows (writes He, invn), 64x64 scaled
// Gram G = c*iv*iv*(K K^T), then T = (I + strict_lower(G))^-1 via 2x2 block
// inversion. Grid = Bq*NCH = 64 blocks, 256 threads.
// Chunk c row j <-> t = 510 - (64c + j); t<0 rows are zero (iv=0).
// ---------------------------------------------------------------------------
__global__ __launch_bounds__(256) void prep_kernel(
    const float* __restrict__ X, const float* __restrict__ gamma,
    const float* __restrict__ beta, float* __restrict__ He,
    float* __restrict__ invn, float* __restrict__ Tout)
{
    extern __shared__ float sh[];
    float* Ks = sh;                  // [64][PSTR]
    float* G  = Ks + 64 * PSTR;      // [64][65]
    float* Ts = G  + 64 * 65;        // [64][65]
    float* Us = Ts + 64 * 65;        // [32][33]
    float* gm = Us + 32 * 33;        // [256]
    float* bt = gm + 256;            // [256]
    float* iv = bt + 256;            // [64]

    const int bId = blockIdx.x >> 3;
    const int cId = blockIdx.x & 7;
    const int tid = threadIdx.x;
    const int w = tid >> 5, lane = tid & 31;

    gm[tid] = gamma[tid];
    bt[tid] = beta[tid];
    __syncthreads();

    // LayerNorm 8 rows per warp
    #pragma unroll
    for (int it = 0; it < 8; it++) {
        const int j = w * 8 + it;
        const int t = 510 - (64 * cId + j);
        if (t < 0) {
            #pragma unroll
            for (int e = 0; e < 8; e++) Ks[j * PSTR + lane + 32 * e] = 0.f;
            if (lane == 0) iv[j] = 0.f;
            continue;
        }
        const float* x = X + ((long)bId * Ld + t) * Hd;
        float v[8], s = 0.f;
        #pragma unroll
        for (int e = 0; e < 8; e++) { v[e] = x[lane + 32 * e]; s += v[e]; }
        #pragma unroll
        for (int o = 16; o > 0; o >>= 1) s += __shfl_xor_sync(0xffffffff, s, o);
        const float mu = s * (1.f / Hd);
        float ss = 0.f;
        #pragma unroll
        for (int e = 0; e < 8; e++) { float d = v[e] - mu; ss += d * d; }
        #pragma unroll
        for (int o = 16; o > 0; o >>= 1) ss += __shfl_xor_sync(0xffffffff, ss, o);
        const float rstd = rsqrtf(ss * (1.f / Hd) + 1e-5f);
        float ns = 0.f;
        float* herow = He + ((long)bId * Ld + t) * Hd;
        #pragma unroll
        for (int e = 0; e < 8; e++) {
            const int c = lane + 32 * e;
            const float o = (v[e] - mu) * rstd * gm[c] + bt[c];
            Ks[j * PSTR + c] = o;
            herow[c] = o;
            ns += o * o;
        }
        #pragma unroll
        for (int o = 16; o > 0; o >>= 1) ns += __shfl_xor_sync(0xffffffff, ns, o);
        if (lane == 0) {
            const float r = 1.f / fmaxf(sqrtf(ns), 1e-12f);
            iv[j] = r;
            invn[bId * Ld + t] = r;
        }
    }
    __syncthreads();

    // Gram 64x64 via 16x16 threads, 4x4 microtile
    {
        const int ty = tid >> 4, tx = tid & 15;
        float acc[4][4];
        #pragma unroll
        for (int i = 0; i < 4; i++)
            #pragma unroll
            for (int j = 0; j < 4; j++) acc[i][j] = 0.f;
        #pragma unroll 4
        for (int kk = 0; kk < 256; kk++) {
            float av[4], bv[4];
            #pragma unroll
            for (int i = 0; i < 4; i++) av[i] = Ks[(4 * ty + i) * PSTR + kk];
            #pragma unroll
            for (int j = 0; j < 4; j++) bv[j] = Ks[(4 * tx + j) * PSTR + kk];
            #pragma unroll
            for (int i = 0; i < 4; i++)
                #pragma unroll
                for (int j = 0; j < 4; j++) acc[i][j] += av[i] * bv[j];
        }
        #pragma unroll
        for (int i = 0; i < 4; i++)
            #pragma unroll
            for (int j = 0; j < 4; j++) {
                const int r = 4 * ty + i, c = 4 * tx + j;
                G[r * 65 + c] = CEMA * iv[r] * iv[c] * acc[i][j];
            }
    }
    __syncthreads();

    // T_A (warp 0), T_B (warp 1): per-column forward substitution.
    if (w == 0) {
        const int c = lane;
        float x[32];
        #pragma unroll
        for (int j = 0; j < 32; j++) {
            float sum = (j == c) ? 1.f : 0.f;
            #pragma unroll
            for (int l = 0; l < 32; l++)
                if (l < j) sum -= G[j * 65 + l] * x[l];
            x[j] = sum;
        }
        #pragma unroll
        for (int j = 0; j < 32; j++) Ts[j * 65 + c] = x[j];
    } else if (w == 1) {
        const int c = lane;
        float x[32];
        #pragma unroll
        for (int j = 0; j < 32; j++) {
            float sum = (j == c) ? 1.f : 0.f;
            #pragma unroll
            for (int l = 0; l < 32; l++)
                if (l < j) sum -= G[(32 + j) * 65 + 32 + l] * x[l];
            x[j] = sum;
        }
        #pragma unroll
        for (int j = 0; j < 32; j++) Ts[(32 + j) * 65 + 32 + c] = x[j];
    } else {
        // zero upper-right block of Ts
        for (int e = tid - 64; e < 1024; e += 192) {
            if (e >= 0) Ts[(e >> 5) * 65 + 32 + (e & 31)] = 0.f;
        }
    }
    __syncthreads();

    // U = C * T_A   (C = G[32:64][0:32])
    #pragma unroll
    for (int q = 0; q < 4; q++) {
        const int e = tid + 256 * q;
        const int r = e >> 5, c = e & 31;
        float s = 0.f;
        #pragma unroll
        for (int l = 0; l < 32; l++)
            s += G[(32 + r) * 65 + l] * Ts[l * 65 + c];
        Us[r * 33 + c] = s;
    }
    __syncthreads();

    // O = -T_B * U  -> lower-left of Ts
    #pragma unroll
    for (int q = 0; q < 4; q++) {
        const int e = tid + 256 * q;
        const int r = e >> 5, c = e & 31;
        float s = 0.f;
        #pragma unroll
        for (int l = 0; l < 32; l++)
            s += Ts[(32 + r) * 65 + 32 + l] * Us[l * 33 + c];
        Ts[(32 + r) * 65 + c] = -s;
    }
    __syncthreads();

    float* Tg = Tout + ((long)(bId * NCH + cId) << 12);
    #pragma unroll
    for (int q = 0; q < 16; q++) {
        const int e = tid + 256 * q;
        Tg[e] = Ts[(e >> 6) * 65 + (e & 63)];
    }
}

// ---------------------------------------------------------------------------
// Chunked backward delta-rule scan, CSZ=64, 8 serial chunks, cp.async
// double buffered. One block per batch, 256 threads.
// Chunk c (ascending = descending time): row j <-> t = 510 - (64c + j).
// ---------------------------------------------------------------------------
__global__ __launch_bounds__(256) void scan_kernel(
    const float* __restrict__ X, const float* __restrict__ He,
    const float* __restrict__ invn, const float* __restrict__ Tin,
    const float* __restrict__ gamma, const float* __restrict__ beta,
    float* __restrict__ mout)
{
    extern __shared__ float sh[];
    float* Kb   = sh;                     // [2][64][KSTR]
    float* Tb   = Kb + 2 * 64 * KSTR;     // [2][64][TSTR]
    float* ivb  = Tb + 2 * 64 * TSTR;     // [2][64]
    float* vsm  = ivb + 128;              // [256]
    float* bsm  = vsm + 256;              // [64]
    float* csm  = bsm + 64;               // [64]
    float* cnsm = csm + 64;               // [64]

    const int bId = blockIdx.x;
    const int tid = threadIdx.x;
    const int w = tid >> 5, lane = tid & 31;
    const float* Hb = He + (long)bId * Ld * Hd;
    const float* In = invn + bId * Ld;
    const float* Tc = Tin + ((long)bId * NCH << 12);

    auto issue = [&](int buf, int c) {
        float* K = Kb + buf * 64 * KSTR;
        // 64 rows x 64 float4
        #pragma unroll
        for (int q = 0; q < 16; q++) {
            const int idx = tid + 256 * q;
            const int j = idx >> 6, c4 = idx & 63;
            const int t = 510 - (64 * c + j);
            float* dst = K + j * KSTR + c4 * 4;
            if (t >= 0) cp16(dst, Hb + (long)t * Hd + c4 * 4);
            else        *(float4*)dst = make_float4(0.f, 0.f, 0.f, 0.f);
        }
        // T: 64x64 = 1024 float4
        #pragma unroll
        for (int q = 0; q < 4; q++) {
            const int idx = tid + 256 * q;
            const int r = idx >> 4, c4 = idx & 15;
            cp16(Tb + buf * 64 * TSTR + r * TSTR + c4 * 4,
                 Tc + ((long)c << 12) + r * 64 + c4 * 4);
        }
        if (tid < 64) {
            const int t = 510 - (64 * c + tid);
            ivb[buf * 64 + tid] = (t >= 0) ? In[t] : 0.f;
        }
    };

    // prologue: start chunk 0 load, LayerNorm the query row (t=511) meanwhile
    issue(0, 0);
    CP_COMMIT();
    {
        const float xq = X[((long)bId * Ld + 511) * Hd + tid];
        float s = xq;
        #pragma unroll
        for (int o = 16; o > 0; o >>= 1) s += __shfl_xor_sync(0xffffffff, s, o);
        if (lane == 0) bsm[w] = s;
        __syncthreads();
        float mu = 0.f;
        #pragma unroll
        for (int e = 0; e < 8; e++) mu += bsm[e];
        mu *= (1.f / Hd);
        const float d = xq - mu;
        float ss = d * d;
        #pragma unroll
        for (int o = 16; o > 0; o >>= 1) ss += __shfl_xor_sync(0xffffffff, ss, o);
        if (lane == 0) csm[w] = ss;
        __syncthreads();
        float var = 0.f;
        #pragma unroll
        for (int e = 0; e < 8; e++) var += csm[e];
        const float rstd = rsqrtf(var * (1.f / Hd) + 1e-5f);
        vsm[tid] = d * rstd * gamma[tid] + beta[tid];
    }
    float mi = 0.f;
    CP_WAIT0();
    __syncthreads();

    const int jrow = tid >> 2, sub = tid & 3;
    int buf = 0;
    #pragma unroll 1
    for (int c = 0; c < NCH; c++) {
        if (c + 1 < NCH) { issue(buf ^ 1, c + 1); CP_COMMIT(); }

        float* K  = Kb + buf * 64 * KSTR;
        float* T  = Tb + buf * 64 * TSTR;
        float* iv = ivb + buf * 64;

        // phase A: b_j = iv_j * (k_j . v), 4 lanes per row
        {
            const float* Kr = K + jrow * KSTR;
            float p0 = 0.f, p1 = 0.f;
            #pragma unroll
            for (int i = 0; i < 64; i += 2) {
                p0 += Kr[sub + 4 * i]       * vsm[sub + 4 * i];
                p1 += Kr[sub + 4 * (i + 1)] * vsm[sub + 4 * (i + 1)];
            }
            float s = p0 + p1;
            s += __shfl_xor_sync(0xffffffff, s, 1);
            s += __shfl_xor_sync(0xffffffff, s, 2);
            if (sub == 0) bsm[jrow] = s * iv[jrow];
        }
        __syncthreads();

        // phase B: s_j = T[j] . b  ->  cs, cs*iv
        {
            const float* Tr = T + jrow * TSTR + sub * 16;
            const float* br = bsm + sub * 16;
            float t0 = 0.f, t1 = 0.f;
            #pragma unroll
            for (int q = 0; q < 16; q += 2) {
                t0 += Tr[q]     * br[q];
                t1 += Tr[q + 1] * br[q + 1];
            }
            float t = t0 + t1;
            t += __shfl_xor_sync(0xffffffff, t, 1);
            t += __shfl_xor_sync(0xffffffff, t, 2);
            if (sub == 0) {
                const float cs = CEMA * t;
                csm[jrow]  = cs;
                cnsm[jrow] = cs * iv[jrow];
            }
        }
        __syncthreads();

        // phase C: rank-64 update of v; accumulate m
        {
            float vi = vsm[tid];
            float dm0 = 0.f, dm1 = 0.f, dv0 = 0.f, dv1 = 0.f;
            #pragma unroll
            for (int j = 0; j < 64; j += 2) {
                const float k0 = K[j * KSTR + tid];
                const float k1 = K[(j + 1) * KSTR + tid];
                dm0 += csm[j] * k0;   dv0 += cnsm[j] * k0;
                dm1 += csm[j + 1] * k1; dv1 += cnsm[j + 1] * k1;
            }
            mi += dm0 + dm1;
            vsm[tid] = vi - (dv0 + dv1);
        }
        if (c + 1 < NCH) CP_WAIT0();
        __syncthreads();
        buf ^= 1;
    }

    mout[bId * Hd + tid] = mi;
}

// ---------------------------------------------------------------------------
// mm = m @ Wrp + brp
// ---------------------------------------------------------------------------
__global__ __launch_bounds__(256) void rp_kernel(
    const float* __restrict__ m, const float* __restrict__ Wrp,
    const float* __restrict__ brp, float* __restrict__ mm)
{
    int b = blockIdx.x, c = threadIdx.x;
    __shared__ float ms[Hd];
    ms[c] = m[b * Hd + c];
    __syncthreads();
    float acc = brp[c];
    #pragma unroll 8
    for (int k = 0; k < Hd; k++) acc += ms[k] * Wrp[k * Hd + c];
    mm[b * Hd + c] = acc;
}

// ---------------------------------------------------------------------------
// out[8,32000] = mm @ Wout + bout
// ---------------------------------------------------------------------------
__global__ __launch_bounds__(128) void out_kernel(
    const float* __restrict__ mm, const float* __restrict__ Wout,
    const float* __restrict__ bout, float* __restrict__ out)
{
    __shared__ float ms[Bq][Hd];
    int tid = threadIdx.x;
    #pragma unroll
    for (int i = tid; i < Bq * Hd; i += 128) ms[i >> 8][i & 255] = mm[i];
    __syncthreads();

    int col = blockIdx.x * 128 + tid;
    float acc[Bq];
    float bo = bout[col];
    #pragma unroll
    for (int b = 0; b < Bq; b++) acc[b] = bo;

    #pragma unroll 4
    for (int k = 0; k < Hd; k++) {
        float w = Wout[(long)k * Vv + col];
        #pragma unroll
        for (int b = 0; b < Bq; b++) acc[b] += ms[b][k] * w;
    }
    #pragma unroll
    for (int b = 0; b < Bq; b++) out[(long)b * Vv + col] = acc[b];
}

// ---------------------------------------------------------------------------
extern "C" void kernel_launch(void* const* d_in, const int* in_sizes, int n_in,
                              void* d_out, int out_size)
{
    const int*   seq   = (const int*)  d_in[0];
    const float* embed = (const float*)d_in[1];
    const float* W1    = (const float*)d_in[2];
    const float* b1    = (const float*)d_in[3];
    const float* W2    = (const float*)d_in[4];
    const float* b2    = (const float*)d_in[5];
    const float* gamma = (const float*)d_in[6];
    const float* beta  = (const float*)d_in[7];
    const float* Wrp   = (const float*)d_in[8];
    const float* brp   = (const float*)d_in[9];
    const float* Wout  = (const float*)d_in[10];
    const float* bout  = (const float*)d_in[11];
    float* out = (float*)d_out;

    float *t1, *x, *he, *invn, *Tm, *m, *mm;
    cudaGetSymbolAddress((void**)&t1,   g_t1);
    cudaGetSymbolAddress((void**)&x,    g_x);
    cudaGetSymbolAddress((void**)&he,   g_he);
    cudaGetSymbolAddress((void**)&invn, g_in);
    cudaGetSymbolAddress((void**)&Tm,   g_T);
    cudaGetSymbolAddress((void**)&m,    g_m);
    cudaGetSymbolAddress((void**)&mm,   g_mm);

    const int prepSmem = (64 * PSTR + 64 * 65 + 64 * 65 + 32 * 33
                          + 256 + 256 + 64) * 4;                     // 107648
    const int scanSmem = (2 * 64 * KSTR + 2 * 64 * TSTR + 128
                          + 256 + 64 * 3) * 4;                       // 170240
    cudaFuncSetAttribute(prep_kernel,
        cudaFuncAttributeMaxDynamicSharedMemorySize, prepSmem);
    cudaFuncSetAttribute(scan_kernel,
        cudaFuncAttributeMaxDynamicSharedMemorySize, scanSmem);

    // 1) t1 = relu(embed[seq] @ W1 + b1)     [4096,512]
    sgemm_kernel<true, true, false><<<dim3(512 / 64, NTOK / 128), 128>>>(
        nullptr, W1, b1, t1, NTOK, 512, Hd, seq, embed);

    // 2) x = t1 @ W2 + b2 + embed[seq]       [4096,256]
    sgemm_kernel<false, false, true><<<dim3(Hd / 64, NTOK / 128), 128>>>(
        t1, W2, b2, x, NTOK, Hd, 512, seq, embed);

    // 3) LN + Gram + chunk inverse T (64 parallel blocks; also writes He, invn)
    prep_kernel<<<Bq * NCH, 256, prepSmem>>>(x, gamma, beta, he, invn, Tm);

    // 4) chunked backward scan -> m (8 blocks, 8 serial chunks)
    scan_kernel<<<Bq, 256, scanSmem>>>(x, he, invn, Tm, gamma, beta, m);

    // 5) mm = m @ Wrp + brp
    rp_kernel<<<Bq, Hd>>>(m, Wrp, brp, mm);

    // 6) out = mm @ Wout + bout
    out_kernel<<<Vv / 128, 128>>>(mm, Wout, bout, out);
}

// round 6
// speedup vs baseline: 2.1952x; 1.3765x over previous
#include <cuda_runtime.h>
#include <cuda_bf16.h>

// Problem constants
#define Hd   256
#define Ld   512
#define Bq   8
#define NTOK 4096            // B*L
#define Vv   32000
#define CEMA 0.05f           // 1 - alpha
#define CSZ  64              // chunk size
#define NCH  8               // chunks per batch
#define KSTR 260             // K-tile smem row stride (scan)
#define PSTR 265             // K-tile smem row stride (prep)
#define TSTR 68              // T smem row stride

typedef __nv_bfloat16 bf16;

// Scratch (device globals)
__device__ bf16  g_A1h[NTOK * Hd],  g_A1l[NTOK * Hd];    // gathered embed, split
__device__ bf16  g_W1h[512 * Hd],   g_W1l[512 * Hd];     // W1^T [512][256]
__device__ bf16  g_W2h[Hd * 512],   g_W2l[Hd * 512];     // W2^T [256][512]
__device__ bf16  g_t1h[NTOK * 512], g_t1l[NTOK * 512];   // relu(h@W1+b1), split
__device__ float g_x [NTOK * Hd];
__device__ float g_he[NTOK * Hd];
__device__ float g_in[NTOK];
__device__ float g_T [Bq * NCH * CSZ * CSZ];
__device__ float g_m [Bq * Hd];
__device__ float g_mm[Bq * Hd];

// cp.async helpers
__device__ __forceinline__ void cp16(void* dst, const void* src) {
    unsigned d = (unsigned)__cvta_generic_to_shared(dst);
    asm volatile("cp.async.ca.shared.global [%0], [%1], 16;\n" :: "r"(d), "l"(src));
}
#define CP_COMMIT() asm volatile("cp.async.commit_group;\n" ::: "memory")
#define CP_WAIT(n)  asm volatile("cp.async.wait_group %0;\n" :: "n"(n) : "memory")

__device__ __forceinline__ void mma_bf16(float* d, const unsigned* a, const unsigned* b) {
    asm volatile(
        "mma.sync.aligned.m16n8k16.row.col.f32.bf16.bf16.f32 "
        "{%0,%1,%2,%3}, {%4,%5,%6,%7}, {%8,%9}, {%0,%1,%2,%3};"
        : "+f"(d[0]), "+f"(d[1]), "+f"(d[2]), "+f"(d[3])
        : "r"(a[0]), "r"(a[1]), "r"(a[2]), "r"(a[3]), "r"(b[0]), "r"(b[1]));
}

__device__ __forceinline__ void split2(float v, bf16& h, bf16& l) {
    h = __float2bfloat16_rn(v);
    l = __float2bfloat16_rn(v - __bfloat162float(h));
}

// ---------------------------------------------------------------------------
// convA: gather embed[seq] rows and split to bf16 hi/lo. 512 blocks x 256 thr.
// ---------------------------------------------------------------------------
__global__ __launch_bounds__(256) void convA_kernel(
    const int* __restrict__ seq, const float* __restrict__ embed,
    bf16* __restrict__ Ah, bf16* __restrict__ Al)
{
    const int c = threadIdx.x;
    #pragma unroll
    for (int i = 0; i < 8; i++) {
        const int r = blockIdx.x * 8 + i;
        const float v = embed[(long)seq[r] * Hd + c];
        bf16 h, l; split2(v, h, l);
        Ah[(long)r * Hd + c] = h;
        Al[(long)r * Hd + c] = l;
    }
}

// ---------------------------------------------------------------------------
// convW: transpose W [K][N] -> Wt [N][K], split hi/lo. Grid (N/32, K/32).
// ---------------------------------------------------------------------------
__global__ __launch_bounds__(256) void convW_kernel(
    const float* __restrict__ W, bf16* __restrict__ Wh, bf16* __restrict__ Wl,
    int K, int N)
{
    __shared__ float tile[32][33];
    const int k0 = blockIdx.y * 32, n0 = blockIdx.x * 32;
    const int tx = threadIdx.x & 31, ty = threadIdx.x >> 5;
    #pragma unroll
    for (int i = 0; i < 4; i++)
        tile[ty + 8 * i][tx] = W[(long)(k0 + ty + 8 * i) * N + n0 + tx];
    __syncthreads();
    #pragma unroll
    for (int i = 0; i < 4; i++) {
        const int row = ty + 8 * i;                 // local n
        const float v = tile[tx][row];
        bf16 h, l; split2(v, h, l);
        Wh[(long)(n0 + row) * K + k0 + tx] = h;
        Wl[(long)(n0 + row) * K + k0 + tx] = l;
    }
}

// ---------------------------------------------------------------------------
// Tensor-core GEMM, bf16x3 split emulating fp32.
// C[M,N] = A[M,K] @ B^T (B given as [N][K] hi/lo bf16).
// Block 64x128, 8 warps (2x4), warp tile 32x32, BK=32, cp.async double buffer.
// MODE 1: +bias, relu, write bf16 hi/lo pair arrays (Ch/Cl).
// MODE 2: +bias, +embed[seq[r]] residual, write fp32 Cf.
// ---------------------------------------------------------------------------
template<int MODE>
__global__ __launch_bounds__(256) void mma_gemm_kernel(
    const bf16* __restrict__ Agh, const bf16* __restrict__ Agl,
    const bf16* __restrict__ Bgh, const bf16* __restrict__ Bgl,
    const float* __restrict__ bias,
    float* __restrict__ Cf, bf16* __restrict__ Ch, bf16* __restrict__ Cl,
    int M, int N, int K,
    const int* __restrict__ seq, const float* __restrict__ embed)
{
    constexpr int BK = 32, STR = 40;
    extern __shared__ bf16 sm[];
    bf16* sA = sm;                      // [2 buf][2 hl][64*STR]
    bf16* sB = sm + 2 * 2 * 64 * STR;   // [2 buf][2 hl][128*STR]

    const int tid = threadIdx.x;
    const int lane = tid & 31;
    const int wid = tid >> 5;
    const int warpM = wid & 1, warpN = wid >> 1;
    const int rowBase = blockIdx.y * 64;
    const int colBase = blockIdx.x * 128;

    auto issue = [&](int buf, int s) {
        const int k0 = s * BK;
        // A: 64 rows x 4 16B-chunks, 1 per thread per matrix
        {
            const int r = tid >> 2, c = (tid & 3) * 8;
            const long goff = (long)(rowBase + r) * K + k0 + c;
            cp16(sA + (buf * 2 + 0) * 64 * STR + r * STR + c, Agh + goff);
            cp16(sA + (buf * 2 + 1) * 64 * STR + r * STR + c, Agl + goff);
        }
        // B: 128 rows x 4 chunks = 512, 2 per thread per matrix
        #pragma unroll
        for (int q = 0; q < 2; q++) {
            const int idx = tid + 256 * q;
            const int n = idx >> 2, c = (idx & 3) * 8;
            const long goff = (long)(colBase + n) * K + k0 + c;
            cp16(sB + (buf * 2 + 0) * 128 * STR + n * STR + c, Bgh + goff);
            cp16(sB + (buf * 2 + 1) * 128 * STR + n * STR + c, Bgl + goff);
        }
    };

    float d[2][4][4];
    #pragma unroll
    for (int mt = 0; mt < 2; mt++)
        #pragma unroll
        for (int nt = 0; nt < 4; nt++)
            #pragma unroll
            for (int e = 0; e < 4; e++) d[mt][nt][e] = 0.f;

    const int nst = K / BK;
    issue(0, 0);
    CP_COMMIT();

    const int lr = lane >> 2;            // fragment row/col group
    const int lk = 2 * (lane & 3);

    for (int s = 0; s < nst; s++) {
        const int buf = s & 1;
        if (s + 1 < nst) { issue(buf ^ 1, s + 1); CP_COMMIT(); CP_WAIT(1); }
        else             { CP_WAIT(0); }
        __syncthreads();

        const bf16* A0 = sA + buf * 2 * 64 * STR;
        const bf16* B0 = sB + buf * 2 * 128 * STR;

        #pragma unroll
        for (int h = 0; h < 2; h++) {
            const int ak = h * 16 + lk;
            unsigned ah[2][4], al[2][4], bh[4][2], bl[4][2];
            #pragma unroll
            for (int mt = 0; mt < 2; mt++) {
                const int base = (warpM * 32 + mt * 16 + lr) * STR + ak;
                ah[mt][0] = *(const unsigned*)(A0 + base);
                ah[mt][1] = *(const unsigned*)(A0 + base + 8 * STR);
                ah[mt][2] = *(const unsigned*)(A0 + base + 8);
                ah[mt][3] = *(const unsigned*)(A0 + base + 8 * STR + 8);
                al[mt][0] = *(const unsigned*)(A0 + 64 * STR + base);
                al[mt][1] = *(const unsigned*)(A0 + 64 * STR + base + 8 * STR);
                al[mt][2] = *(const unsigned*)(A0 + 64 * STR + base + 8);
                al[mt][3] = *(const unsigned*)(A0 + 64 * STR + base + 8 * STR + 8);
            }
            #pragma unroll
            for (int nt = 0; nt < 4; nt++) {
                const int bbase = (warpN * 32 + nt * 8 + lr) * STR + ak;
                bh[nt][0] = *(const unsigned*)(B0 + bbase);
                bh[nt][1] = *(const unsigned*)(B0 + bbase + 8);
                bl[nt][0] = *(const unsigned*)(B0 + 128 * STR + bbase);
                bl[nt][1] = *(const unsigned*)(B0 + 128 * STR + bbase + 8);
            }
            #pragma unroll
            for (int mt = 0; mt < 2; mt++)
                #pragma unroll
                for (int nt = 0; nt < 4; nt++) {
                    mma_bf16(d[mt][nt], ah[mt], bh[nt]);
                    mma_bf16(d[mt][nt], ah[mt], bl[nt]);
                    mma_bf16(d[mt][nt], al[mt], bh[nt]);
                }
        }
        __syncthreads();
    }

    // epilogue
    #pragma unroll
    for (int mt = 0; mt < 2; mt++) {
        #pragma unroll
        for (int nt = 0; nt < 4; nt++) {
            const int cc = colBase + warpN * 32 + nt * 8 + lk;
            const float b0 = bias[cc], b1 = bias[cc + 1];
            #pragma unroll
            for (int half = 0; half < 2; half++) {
                const int r = rowBase + warpM * 32 + mt * 16 + lr + half * 8;
                float v0 = d[mt][nt][half * 2 + 0] + b0;
                float v1 = d[mt][nt][half * 2 + 1] + b1;
                if (MODE == 1) {
                    v0 = fmaxf(v0, 0.f); v1 = fmaxf(v1, 0.f);
                    bf16 h0, l0, h1, l1;
                    split2(v0, h0, l0); split2(v1, h1, l1);
                    const long off = (long)r * N + cc;
                    *(__nv_bfloat162*)(Ch + off) = __halves2bfloat162(h0, h1);
                    *(__nv_bfloat162*)(Cl + off) = __halves2bfloat162(l0, l1);
                } else {
                    const float* erow = embed + (long)seq[r] * Hd + cc;
                    v0 += erow[0]; v1 += erow[1];
                    *(float2*)(Cf + (long)r * N + cc) = make_float2(v0, v1);
                }
            }
        }
    }
}

// ---------------------------------------------------------------------------
// Prep kernel (unchanged from R5): LN + 64x64 Gram + T = (I+cL)^-1
// ---------------------------------------------------------------------------
__global__ __launch_bounds__(256) void prep_kernel(
    const float* __restrict__ X, const float* __restrict__ gamma,
    const float* __restrict__ beta, float* __restrict__ He,
    float* __restrict__ invn, float* __restrict__ Tout)
{
    extern __shared__ float sh[];
    float* Ks = sh;                  // [64][PSTR]
    float* G  = Ks + 64 * PSTR;      // [64][65]
    float* Ts = G  + 64 * 65;        // [64][65]
    float* Us = Ts + 64 * 65;        // [32][33]
    float* gm = Us + 32 * 33;        // [256]
    float* bt = gm + 256;            // [256]
    float* iv = bt + 256;            // [64]

    const int bId = blockIdx.x >> 3;
    const int cId = blockIdx.x & 7;
    const int tid = threadIdx.x;
    const int w = tid >> 5, lane = tid & 31;

    gm[tid] = gamma[tid];
    bt[tid] = beta[tid];
    __syncthreads();

    #pragma unroll
    for (int it = 0; it < 8; it++) {
        const int j = w * 8 + it;
        const int t = 510 - (64 * cId + j);
        if (t < 0) {
            #pragma unroll
            for (int e = 0; e < 8; e++) Ks[j * PSTR + lane + 32 * e] = 0.f;
            if (lane == 0) iv[j] = 0.f;
            continue;
        }
        const float* x = X + ((long)bId * Ld + t) * Hd;
        float v[8], s = 0.f;
        #pragma unroll
        for (int e = 0; e < 8; e++) { v[e] = x[lane + 32 * e]; s += v[e]; }
        #pragma unroll
        for (int o = 16; o > 0; o >>= 1) s += __shfl_xor_sync(0xffffffff, s, o);
        const float mu = s * (1.f / Hd);
        float ss = 0.f;
        #pragma unroll
        for (int e = 0; e < 8; e++) { float dd = v[e] - mu; ss += dd * dd; }
        #pragma unroll
        for (int o = 16; o > 0; o >>= 1) ss += __shfl_xor_sync(0xffffffff, ss, o);
        const float rstd = rsqrtf(ss * (1.f / Hd) + 1e-5f);
        float ns = 0.f;
        float* herow = He + ((long)bId * Ld + t) * Hd;
        #pragma unroll
        for (int e = 0; e < 8; e++) {
            const int c = lane + 32 * e;
            const float o = (v[e] - mu) * rstd * gm[c] + bt[c];
            Ks[j * PSTR + c] = o;
            herow[c] = o;
            ns += o * o;
        }
        #pragma unroll
        for (int o = 16; o > 0; o >>= 1) ns += __shfl_xor_sync(0xffffffff, ns, o);
        if (lane == 0) {
            const float r = 1.f / fmaxf(sqrtf(ns), 1e-12f);
            iv[j] = r;
            invn[bId * Ld + t] = r;
        }
    }
    __syncthreads();

    {
        const int ty = tid >> 4, tx = tid & 15;
        float acc[4][4];
        #pragma unroll
        for (int i = 0; i < 4; i++)
            #pragma unroll
            for (int j = 0; j < 4; j++) acc[i][j] = 0.f;
        #pragma unroll 4
        for (int kk = 0; kk < 256; kk++) {
            float av[4], bv[4];
            #pragma unroll
            for (int i = 0; i < 4; i++) av[i] = Ks[(4 * ty + i) * PSTR + kk];
            #pragma unroll
            for (int j = 0; j < 4; j++) bv[j] = Ks[(4 * tx + j) * PSTR + kk];
            #pragma unroll
            for (int i = 0; i < 4; i++)
                #pragma unroll
                for (int j = 0; j < 4; j++) acc[i][j] += av[i] * bv[j];
        }
        #pragma unroll
        for (int i = 0; i < 4; i++)
            #pragma unroll
            for (int j = 0; j < 4; j++) {
                const int r = 4 * ty + i, c = 4 * tx + j;
                G[r * 65 + c] = CEMA * iv[r] * iv[c] * acc[i][j];
            }
    }
    __syncthreads();

    if (w == 0) {
        const int c = lane;
        float x[32];
        #pragma unroll
        for (int j = 0; j < 32; j++) {
            float sum = (j == c) ? 1.f : 0.f;
            #pragma unroll
            for (int l = 0; l < 32; l++)
                if (l < j) sum -= G[j * 65 + l] * x[l];
            x[j] = sum;
        }
        #pragma unroll
        for (int j = 0; j < 32; j++) Ts[j * 65 + c] = x[j];
    } else if (w == 1) {
        const int c = lane;
        float x[32];
        #pragma unroll
        for (int j = 0; j < 32; j++) {
            float sum = (j == c) ? 1.f : 0.f;
            #pragma unroll
            for (int l = 0; l < 32; l++)
                if (l < j) sum -= G[(32 + j) * 65 + 32 + l] * x[l];
            x[j] = sum;
        }
        #pragma unroll
        for (int j = 0; j < 32; j++) Ts[(32 + j) * 65 + 32 + c] = x[j];
    } else {
        for (int e = tid - 64; e < 1024; e += 192) {
            if (e >= 0) Ts[(e >> 5) * 65 + 32 + (e & 31)] = 0.f;
        }
    }
    __syncthreads();

    #pragma unroll
    for (int q = 0; q < 4; q++) {
        const int e = tid + 256 * q;
        const int r = e >> 5, c = e & 31;
        float s = 0.f;
        #pragma unroll
        for (int l = 0; l < 32; l++)
            s += G[(32 + r) * 65 + l] * Ts[l * 65 + c];
        Us[r * 33 + c] = s;
    }
    __syncthreads();

    #pragma unroll
    for (int q = 0; q < 4; q++) {
        const int e = tid + 256 * q;
        const int r = e >> 5, c = e & 31;
        float s = 0.f;
        #pragma unroll
        for (int l = 0; l < 32; l++)
            s += Ts[(32 + r) * 65 + 32 + l] * Us[l * 33 + c];
        Ts[(32 + r) * 65 + c] = -s;
    }
    __syncthreads();

    float* Tg = Tout + ((long)(bId * NCH + cId) << 12);
    #pragma unroll
    for (int q = 0; q < 16; q++) {
        const int e = tid + 256 * q;
        Tg[e] = Ts[(e >> 6) * 65 + (e & 63)];
    }
}

// ---------------------------------------------------------------------------
// Chunked backward scan (unchanged from R5)
// ---------------------------------------------------------------------------
__global__ __launch_bounds__(256) void scan_kernel(
    const float* __restrict__ X, const float* __restrict__ He,
    const float* __restrict__ invn, const float* __restrict__ Tin,
    const float* __restrict__ gamma, const float* __restrict__ beta,
    float* __restrict__ mout)
{
    extern __shared__ float sh[];
    float* Kb   = sh;                     // [2][64][KSTR]
    float* Tb   = Kb + 2 * 64 * KSTR;     // [2][64][TSTR]
    float* ivb  = Tb + 2 * 64 * TSTR;     // [2][64]
    float* vsm  = ivb + 128;              // [256]
    float* bsm  = vsm + 256;              // [64]
    float* csm  = bsm + 64;               // [64]
    float* cnsm = csm + 64;               // [64]

    const int bId = blockIdx.x;
    const int tid = threadIdx.x;
    const int w = tid >> 5, lane = tid & 31;
    const float* Hb = He + (long)bId * Ld * Hd;
    const float* In = invn + bId * Ld;
    const float* Tc = Tin + ((long)bId * NCH << 12);

    auto issue = [&](int buf, int c) {
        float* K = Kb + buf * 64 * KSTR;
        #pragma unroll
        for (int q = 0; q < 16; q++) {
            const int idx = tid + 256 * q;
            const int j = idx >> 6, c4 = idx & 63;
            const int t = 510 - (64 * c + j);
            float* dst = K + j * KSTR + c4 * 4;
            if (t >= 0) cp16(dst, Hb + (long)t * Hd + c4 * 4);
            else        *(float4*)dst = make_float4(0.f, 0.f, 0.f, 0.f);
        }
        #pragma unroll
        for (int q = 0; q < 4; q++) {
            const int idx = tid + 256 * q;
            const int r = idx >> 4, c4 = idx & 15;
            cp16(Tb + buf * 64 * TSTR + r * TSTR + c4 * 4,
                 Tc + ((long)c << 12) + r * 64 + c4 * 4);
        }
        if (tid < 64) {
            const int t = 510 - (64 * c + tid);
            ivb[buf * 64 + tid] = (t >= 0) ? In[t] : 0.f;
        }
    };

    issue(0, 0);
    CP_COMMIT();
    {
        const float xq = X[((long)bId * Ld + 511) * Hd + tid];
        float s = xq;
        #pragma unroll
        for (int o = 16; o > 0; o >>= 1) s += __shfl_xor_sync(0xffffffff, s, o);
        if (lane == 0) bsm[w] = s;
        __syncthreads();
        float mu = 0.f;
        #pragma unroll
        for (int e = 0; e < 8; e++) mu += bsm[e];
        mu *= (1.f / Hd);
        const float d = xq - mu;
        float ss = d * d;
        #pragma unroll
        for (int o = 16; o > 0; o >>= 1) ss += __shfl_xor_sync(0xffffffff, ss, o);
        if (lane == 0) csm[w] = ss;
        __syncthreads();
        float var = 0.f;
        #pragma unroll
        for (int e = 0; e < 8; e++) var += csm[e];
        const float rstd = rsqrtf(var * (1.f / Hd) + 1e-5f);
        vsm[tid] = d * rstd * gamma[tid] + beta[tid];
    }
    float mi = 0.f;
    CP_WAIT(0);
    __syncthreads();

    const int jrow = tid >> 2, sub = tid & 3;
    int buf = 0;
    #pragma unroll 1
    for (int c = 0; c < NCH; c++) {
        if (c + 1 < NCH) { issue(buf ^ 1, c + 1); CP_COMMIT(); }

        float* K  = Kb + buf * 64 * KSTR;
        float* T  = Tb + buf * 64 * TSTR;
        float* iv = ivb + buf * 64;

        {
            const float* Kr = K + jrow * KSTR;
            float p0 = 0.f, p1 = 0.f;
            #pragma unroll
            for (int i = 0; i < 64; i += 2) {
                p0 += Kr[sub + 4 * i]       * vsm[sub + 4 * i];
                p1 += Kr[sub + 4 * (i + 1)] * vsm[sub + 4 * (i + 1)];
            }
            float s = p0 + p1;
            s += __shfl_xor_sync(0xffffffff, s, 1);
            s += __shfl_xor_sync(0xffffffff, s, 2);
            if (sub == 0) bsm[jrow] = s * iv[jrow];
        }
        __syncthreads();

        {
            const float* Tr = T + jrow * TSTR + sub * 16;
            const float* br = bsm + sub * 16;
            float t0 = 0.f, t1 = 0.f;
            #pragma unroll
            for (int q = 0; q < 16; q += 2) {
                t0 += Tr[q]     * br[q];
                t1 += Tr[q + 1] * br[q + 1];
            }
            float t = t0 + t1;
            t += __shfl_xor_sync(0xffffffff, t, 1);
            t += __shfl_xor_sync(0xffffffff, t, 2);
            if (sub == 0) {
                const float cs = CEMA * t;
                csm[jrow]  = cs;
                cnsm[jrow] = cs * iv[jrow];
            }
        }
        __syncthreads();

        {
            float vi = vsm[tid];
            float dm0 = 0.f, dm1 = 0.f, dv0 = 0.f, dv1 = 0.f;
            #pragma unroll
            for (int j = 0; j < 64; j += 2) {
                const float k0 = K[j * KSTR + tid];
                const float k1 = K[(j + 1) * KSTR + tid];
                dm0 += csm[j] * k0;     dv0 += cnsm[j] * k0;
                dm1 += csm[j + 1] * k1; dv1 += cnsm[j + 1] * k1;
            }
            mi += dm0 + dm1;
            vsm[tid] = vi - (dv0 + dv1);
        }
        if (c + 1 < NCH) CP_WAIT(0);
        __syncthreads();
        buf ^= 1;
    }

    mout[bId * Hd + tid] = mi;
}

// ---------------------------------------------------------------------------
// mm = m @ Wrp + brp
// ---------------------------------------------------------------------------
__global__ __launch_bounds__(256) void rp_kernel(
    const float* __restrict__ m, const float* __restrict__ Wrp,
    const float* __restrict__ brp, float* __restrict__ mm)
{
    int b = blockIdx.x, c = threadIdx.x;
    __shared__ float ms[Hd];
    ms[c] = m[b * Hd + c];
    __syncthreads();
    float acc = brp[c];
    #pragma unroll 8
    for (int k = 0; k < Hd; k++) acc += ms[k] * Wrp[k * Hd + c];
    mm[b * Hd + c] = acc;
}

// ---------------------------------------------------------------------------
// out[8,32000] = mm @ Wout + bout
// ---------------------------------------------------------------------------
__global__ __launch_bounds__(128) void out_kernel(
    const float* __restrict__ mm, const float* __restrict__ Wout,
    const float* __restrict__ bout, float* __restrict__ out)
{
    __shared__ float ms[Bq][Hd];
    int tid = threadIdx.x;
    #pragma unroll
    for (int i = tid; i < Bq * Hd; i += 128) ms[i >> 8][i & 255] = mm[i];
    __syncthreads();

    int col = blockIdx.x * 128 + tid;
    float acc[Bq];
    float bo = bout[col];
    #pragma unroll
    for (int b = 0; b < Bq; b++) acc[b] = bo;

    #pragma unroll 4
    for (int k = 0; k < Hd; k++) {
        float w = Wout[(long)k * Vv + col];
        #pragma unroll
        for (int b = 0; b < Bq; b++) acc[b] += ms[b][k] * w;
    }
    #pragma unroll
    for (int b = 0; b < Bq; b++) out[(long)b * Vv + col] = acc[b];
}

// ---------------------------------------------------------------------------
extern "C" void kernel_launch(void* const* d_in, const int* in_sizes, int n_in,
                              void* d_out, int out_size)
{
    const int*   seq   = (const int*)  d_in[0];
    const float* embed = (const float*)d_in[1];
    const float* W1    = (const float*)d_in[2];
    const float* b1    = (const float*)d_in[3];
    const float* W2    = (const float*)d_in[4];
    const float* b2    = (const float*)d_in[5];
    const float* gamma = (const float*)d_in[6];
    const float* beta  = (const float*)d_in[7];
    const float* Wrp   = (const float*)d_in[8];
    const float* brp   = (const float*)d_in[9];
    const float* Wout  = (const float*)d_in[10];
    const float* bout  = (const float*)d_in[11];
    float* out = (float*)d_out;

    bf16 *A1h, *A1l, *W1h, *W1l, *W2h, *W2l, *t1h, *t1l;
    float *x, *he, *invn, *Tm, *m, *mm;
    cudaGetSymbolAddress((void**)&A1h, g_A1h);
    cudaGetSymbolAddress((void**)&A1l, g_A1l);
    cudaGetSymbolAddress((void**)&W1h, g_W1h);
    cudaGetSymbolAddress((void**)&W1l, g_W1l);
    cudaGetSymbolAddress((void**)&W2h, g_W2h);
    cudaGetSymbolAddress((void**)&W2l, g_W2l);
    cudaGetSymbolAddress((void**)&t1h, g_t1h);
    cudaGetSymbolAddress((void**)&t1l, g_t1l);
    cudaGetSymbolAddress((void**)&x,    g_x);
    cudaGetSymbolAddress((void**)&he,   g_he);
    cudaGetSymbolAddress((void**)&invn, g_in);
    cudaGetSymbolAddress((void**)&Tm,   g_T);
    cudaGetSymbolAddress((void**)&m,    g_m);
    cudaGetSymbolAddress((void**)&mm,   g_mm);

    const int gemmSmem = (2 * 2 * 64 * 40 + 2 * 2 * 128 * 40) * 2;   // 61440
    const int prepSmem = (64 * PSTR + 64 * 65 + 64 * 65 + 32 * 33
                          + 256 + 256 + 64) * 4;
    const int scanSmem = (2 * 64 * KSTR + 2 * 64 * TSTR + 128
                          + 256 + 64 * 3) * 4;
    cudaFuncSetAttribute(mma_gemm_kernel<1>,
        cudaFuncAttributeMaxDynamicSharedMemorySize, gemmSmem);
    cudaFuncSetAttribute(mma_gemm_kernel<2>,
        cudaFuncAttributeMaxDynamicSharedMemorySize, gemmSmem);
    cudaFuncSetAttribute(prep_kernel,
        cudaFuncAttributeMaxDynamicSharedMemorySize, prepSmem);
    cudaFuncSetAttribute(scan_kernel,
        cudaFuncAttributeMaxDynamicSharedMemorySize, scanSmem);

    // 0) conversions / transposes
    convA_kernel<<<NTOK / 8, 256>>>(seq, embed, A1h, A1l);
    convW_kernel<<<dim3(512 / 32, Hd / 32), 256>>>(W1, W1h, W1l, Hd, 512);
    convW_kernel<<<dim3(Hd / 32, 512 / 32), 256>>>(W2, W2h, W2l, 512, Hd);

    // 1) t1 = relu(A1 @ W1 + b1) -> bf16 hi/lo    [4096,512]
    mma_gemm_kernel<1><<<dim3(512 / 128, NTOK / 64), 256, gemmSmem>>>(
        A1h, A1l, W1h, W1l, b1, nullptr, t1h, t1l,
        NTOK, 512, Hd, seq, embed);

    // 2) x = t1 @ W2 + b2 + embed[seq]            [4096,256]
    mma_gemm_kernel<2><<<dim3(Hd / 128, NTOK / 64), 256, gemmSmem>>>(
        t1h, t1l, W2h, W2l, b2, x, nullptr, nullptr,
        NTOK, Hd, 512, seq, embed);

    // 3) LN + Gram + chunk inverse T
    prep_kernel<<<Bq * NCH, 256, prepSmem>>>(x, gamma, beta, he, invn, Tm);

    // 4) chunked backward scan -> m
    scan_kernel<<<Bq, 256, scanSmem>>>(x, he, invn, Tm, gamma, beta, m);

    // 5) mm = m @ Wrp + brp
    rp_kernel<<<Bq, Hd>>>(m, Wrp, brp, mm);

    // 6) out = mm @ Wout + bout
    out_kernel<<<Vv / 128, 128>>>(mm, Wout, bout, out);
}

// round 7
// speedup vs baseline: 2.3283x; 1.0606x over previous
#include <cuda_runtime.h>
#include <cuda_bf16.h>

// Problem constants
#define Hd   256
#define Ld   512
#define Bq   8
#define NTOK 4096            // B*L
#define Vv   32000
#define CEMA 0.05f           // 1 - alpha
#define CSZ  64              // chunk size
#define NCH  8               // chunks per batch
#define KSTR 260             // K-tile smem row stride (scan)
#define PSTR 265             // K-tile smem row stride (prep)
#define TSTR 68              // T smem row stride

typedef __nv_bfloat16 bf16;

// Scratch (device globals)
__device__ bf16  g_A1h[NTOK * Hd],  g_A1l[NTOK * Hd];    // gathered embed, split
__device__ bf16  g_W1h[512 * Hd],   g_W1l[512 * Hd];     // W1^T [512][256]
__device__ bf16  g_W2h[Hd * 512],   g_W2l[Hd * 512];     // W2^T [256][512]
__device__ bf16  g_t1h[NTOK * 512], g_t1l[NTOK * 512];   // relu(h@W1+b1), split
__device__ float g_x [NTOK * Hd];
__device__ float g_he[NTOK * Hd];
__device__ float g_in[NTOK];
__device__ float g_T [Bq * NCH * CSZ * CSZ];
__device__ float g_mm[Bq * Hd];

// cp.async helpers
__device__ __forceinline__ void cp16(void* dst, const void* src) {
    unsigned d = (unsigned)__cvta_generic_to_shared(dst);
    asm volatile("cp.async.ca.shared.global [%0], [%1], 16;\n" :: "r"(d), "l"(src));
}
#define CP_COMMIT() asm volatile("cp.async.commit_group;\n" ::: "memory")
#define CP_WAIT(n)  asm volatile("cp.async.wait_group %0;\n" :: "n"(n) : "memory")

__device__ __forceinline__ void mma_bf16(float* d, const unsigned* a, const unsigned* b) {
    asm volatile(
        "mma.sync.aligned.m16n8k16.row.col.f32.bf16.bf16.f32 "
        "{%0,%1,%2,%3}, {%4,%5,%6,%7}, {%8,%9}, {%0,%1,%2,%3};"
        : "+f"(d[0]), "+f"(d[1]), "+f"(d[2]), "+f"(d[3])
        : "r"(a[0]), "r"(a[1]), "r"(a[2]), "r"(a[3]), "r"(b[0]), "r"(b[1]));
}

__device__ __forceinline__ void ldsm4(unsigned* r, unsigned addr) {
    asm volatile("ldmatrix.sync.aligned.m8n8.x4.shared.b16 {%0,%1,%2,%3}, [%4];"
        : "=r"(r[0]), "=r"(r[1]), "=r"(r[2]), "=r"(r[3]) : "r"(addr));
}

__device__ __forceinline__ void split2(float v, bf16& h, bf16& l) {
    h = __float2bfloat16_rn(v);
    l = __float2bfloat16_rn(v - __bfloat162float(h));
}

// ---------------------------------------------------------------------------
// Combined conversion kernel:
//  blocks [0,512):    gather embed[seq] rows -> A1 hi/lo
//  blocks [512,640):  W1 [256][512] -> W1^T hi/lo  (grid 16 x 8)
//  blocks [640,768):  W2 [512][256] -> W2^T hi/lo  (grid 8 x 16)
// ---------------------------------------------------------------------------
__global__ __launch_bounds__(256) void conv_kernel(
    const int* __restrict__ seq, const float* __restrict__ embed,
    const float* __restrict__ W1, const float* __restrict__ W2,
    bf16* __restrict__ Ah, bf16* __restrict__ Al,
    bf16* __restrict__ W1h, bf16* __restrict__ W1l,
    bf16* __restrict__ W2h, bf16* __restrict__ W2l)
{
    __shared__ float tile[32][33];
    const int b = blockIdx.x;
    if (b < 512) {
        const int c = threadIdx.x;
        #pragma unroll
        for (int i = 0; i < 8; i++) {
            const int r = b * 8 + i;
            const float v = embed[(long)seq[r] * Hd + c];
            bf16 h, l; split2(v, h, l);
            Ah[(long)r * Hd + c] = h;
            Al[(long)r * Hd + c] = l;
        }
        return;
    }
    const float* W; bf16 *Wh, *Wl; int K, N, n0, k0;
    if (b < 640) {
        const int p = b - 512;
        W = W1; Wh = W1h; Wl = W1l; K = Hd; N = 512;
        n0 = (p & 15) * 32; k0 = (p >> 4) * 32;
    } else {
        const int p = b - 640;
        W = W2; Wh = W2h; Wl = W2l; K = 512; N = Hd;
        n0 = (p & 7) * 32; k0 = (p >> 3) * 32;
    }
    const int tx = threadIdx.x & 31, ty = threadIdx.x >> 5;
    #pragma unroll
    for (int i = 0; i < 4; i++)
        tile[ty + 8 * i][tx] = W[(long)(k0 + ty + 8 * i) * N + n0 + tx];
    __syncthreads();
    #pragma unroll
    for (int i = 0; i < 4; i++) {
        const int row = ty + 8 * i;                 // local n
        const float v = tile[tx][row];
        bf16 h, l; split2(v, h, l);
        Wh[(long)(n0 + row) * K + k0 + tx] = h;
        Wl[(long)(n0 + row) * K + k0 + tx] = l;
    }
}

// ---------------------------------------------------------------------------
// Tensor-core GEMM, bf16x3 split emulating fp32, ldmatrix fragment loads.
// C[M,N] = A[M,K] @ B^T (B given as [N][K] hi/lo bf16).
// Block 64x128, 8 warps (2x4), warp tile 32x32, BK=32, cp.async double buffer.
// MODE 1: +bias, relu, write bf16 hi/lo (Ch/Cl).
// MODE 2: +bias, +embed[seq[r]] residual, write fp32 Cf.
// ---------------------------------------------------------------------------
template<int MODE>
__global__ __launch_bounds__(256, 2) void mma_gemm_kernel(
    const bf16* __restrict__ Agh, const bf16* __restrict__ Agl,
    const bf16* __restrict__ Bgh, const bf16* __restrict__ Bgl,
    const float* __restrict__ bias,
    float* __restrict__ Cf, bf16* __restrict__ Ch, bf16* __restrict__ Cl,
    int M, int N, int K,
    const int* __restrict__ seq, const float* __restrict__ embed)
{
    constexpr int BK = 32, STR = 40;
    extern __shared__ bf16 sm[];
    bf16* sA = sm;                      // [2 buf][2 hl][64*STR]
    bf16* sB = sm + 2 * 2 * 64 * STR;   // [2 buf][2 hl][128*STR]

    const int tid = threadIdx.x;
    const int lane = tid & 31;
    const int wid = tid >> 5;
    const int warpM = wid & 1, warpN = wid >> 1;
    const int rowBase = blockIdx.y * 64;
    const int colBase = blockIdx.x * 128;

    auto issue = [&](int buf, int s) {
        const int k0 = s * BK;
        {
            const int r = tid >> 2, c = (tid & 3) * 8;
            const long goff = (long)(rowBase + r) * K + k0 + c;
            cp16(sA + (buf * 2 + 0) * 64 * STR + r * STR + c, Agh + goff);
            cp16(sA + (buf * 2 + 1) * 64 * STR + r * STR + c, Agl + goff);
        }
        #pragma unroll
        for (int q = 0; q < 2; q++) {
            const int idx = tid + 256 * q;
            const int n = idx >> 2, c = (idx & 3) * 8;
            const long goff = (long)(colBase + n) * K + k0 + c;
            cp16(sB + (buf * 2 + 0) * 128 * STR + n * STR + c, Bgh + goff);
            cp16(sB + (buf * 2 + 1) * 128 * STR + n * STR + c, Bgl + goff);
        }
    };

    float d[2][4][4];
    #pragma unroll
    for (int mt = 0; mt < 2; mt++)
        #pragma unroll
        for (int nt = 0; nt < 4; nt++)
            #pragma unroll
            for (int e = 0; e < 4; e++) d[mt][nt][e] = 0.f;

    const int nst = K / BK;
    issue(0, 0);
    CP_COMMIT();

    // ldmatrix lane geometry
    const unsigned smemBase = (unsigned)__cvta_generic_to_shared(sm);
    const int lane8 = lane & 7, ls = lane >> 3;
    const int aRow = warpM * 32 + lane8 + ((ls & 1) << 3);   // + mt*16
    const int aCol = (ls & 2) << 2;                          // 0 or 8
    const int bRow = warpN * 32 + lane8 + ((ls & 2) << 2);   // + p*16
    const int bCol = (ls & 1) << 3;                          // 0 or 8
    const unsigned sBbase = smemBase + 2u * (2 * 2 * 64 * STR);

    for (int s = 0; s < nst; s++) {
        const int buf = s & 1;
        if (s + 1 < nst) { issue(buf ^ 1, s + 1); CP_COMMIT(); CP_WAIT(1); }
        else             { CP_WAIT(0); }
        __syncthreads();

        const unsigned aBuf = smemBase + 2u * (buf * 2 * 64 * STR);
        const unsigned bBuf = sBbase   + 2u * (buf * 2 * 128 * STR);

        #pragma unroll
        for (int h = 0; h < 2; h++) {
            const int hk = h * 16;
            unsigned ah[2][4], al[2][4], bh[2][4], bl[2][4];
            #pragma unroll
            for (int mt = 0; mt < 2; mt++) {
                const unsigned off = 2u * ((aRow + mt * 16) * STR + hk + aCol);
                ldsm4(ah[mt], aBuf + off);
                ldsm4(al[mt], aBuf + 2u * (64 * STR) + off);
            }
            #pragma unroll
            for (int p = 0; p < 2; p++) {
                const unsigned off = 2u * ((bRow + p * 16) * STR + hk + bCol);
                ldsm4(bh[p], bBuf + off);
                ldsm4(bl[p], bBuf + 2u * (128 * STR) + off);
            }
            #pragma unroll
            for (int mt = 0; mt < 2; mt++)
                #pragma unroll
                for (int nt = 0; nt < 4; nt++) {
                    const int p = nt >> 1, o = (nt & 1) * 2;
                    mma_bf16(d[mt][nt], ah[mt], &bh[p][o]);
                    mma_bf16(d[mt][nt], ah[mt], &bl[p][o]);
                    mma_bf16(d[mt][nt], al[mt], &bh[p][o]);
                }
        }
        __syncthreads();
    }

    // epilogue
    const int lr = lane >> 2;
    const int lk = 2 * (lane & 3);
    #pragma unroll
    for (int mt = 0; mt < 2; mt++) {
        #pragma unroll
        for (int nt = 0; nt < 4; nt++) {
            const int cc = colBase + warpN * 32 + nt * 8 + lk;
            const float b0 = bias[cc], b1 = bias[cc + 1];
            #pragma unroll
            for (int half = 0; half < 2; half++) {
                const int r = rowBase + warpM * 32 + mt * 16 + lr + half * 8;
                float v0 = d[mt][nt][half * 2 + 0] + b0;
                float v1 = d[mt][nt][half * 2 + 1] + b1;
                if (MODE == 1) {
                    v0 = fmaxf(v0, 0.f); v1 = fmaxf(v1, 0.f);
                    bf16 h0, l0, h1, l1;
                    split2(v0, h0, l0); split2(v1, h1, l1);
                    const long off = (long)r * N + cc;
                    *(__nv_bfloat162*)(Ch + off) = __halves2bfloat162(h0, h1);
                    *(__nv_bfloat162*)(Cl + off) = __halves2bfloat162(l0, l1);
                } else {
                    const float* erow = embed + (long)seq[r] * Hd + cc;
                    v0 += erow[0]; v1 += erow[1];
                    *(float2*)(Cf + (long)r * N + cc) = make_float2(v0, v1);
                }
            }
        }
    }
}

// ---------------------------------------------------------------------------
// Prep kernel: LN + 64x64 Gram + T = (I+cL)^-1   (unchanged)
// ---------------------------------------------------------------------------
__global__ __launch_bounds__(256) void prep_kernel(
    const float* __restrict__ X, const float* __restrict__ gamma,
    const float* __restrict__ beta, float* __restrict__ He,
    float* __restrict__ invn, float* __restrict__ Tout)
{
    extern __shared__ float sh[];
    float* Ks = sh;                  // [64][PSTR]
    float* G  = Ks + 64 * PSTR;      // [64][65]
    float* Ts = G  + 64 * 65;        // [64][65]
    float* Us = Ts + 64 * 65;        // [32][33]
    float* gm = Us + 32 * 33;        // [256]
    float* bt = gm + 256;            // [256]
    float* iv = bt + 256;            // [64]

    const int bId = blockIdx.x >> 3;
    const int cId = blockIdx.x & 7;
    const int tid = threadIdx.x;
    const int w = tid >> 5, lane = tid & 31;

    gm[tid] = gamma[tid];
    bt[tid] = beta[tid];
    __syncthreads();

    #pragma unroll
    for (int it = 0; it < 8; it++) {
        const int j = w * 8 + it;
        const int t = 510 - (64 * cId + j);
        if (t < 0) {
            #pragma unroll
            for (int e = 0; e < 8; e++) Ks[j * PSTR + lane + 32 * e] = 0.f;
            if (lane == 0) iv[j] = 0.f;
            continue;
        }
        const float* x = X + ((long)bId * Ld + t) * Hd;
        float v[8], s = 0.f;
        #pragma unroll
        for (int e = 0; e < 8; e++) { v[e] = x[lane + 32 * e]; s += v[e]; }
        #pragma unroll
        for (int o = 16; o > 0; o >>= 1) s += __shfl_xor_sync(0xffffffff, s, o);
        const float mu = s * (1.f / Hd);
        float ss = 0.f;
        #pragma unroll
        for (int e = 0; e < 8; e++) { float dd = v[e] - mu; ss += dd * dd; }
        #pragma unroll
        for (int o = 16; o > 0; o >>= 1) ss += __shfl_xor_sync(0xffffffff, ss, o);
        const float rstd = rsqrtf(ss * (1.f / Hd) + 1e-5f);
        float ns = 0.f;
        float* herow = He + ((long)bId * Ld + t) * Hd;
        #pragma unroll
        for (int e = 0; e < 8; e++) {
            const int c = lane + 32 * e;
            const float o = (v[e] - mu) * rstd * gm[c] + bt[c];
            Ks[j * PSTR + c] = o;
            herow[c] = o;
            ns += o * o;
        }
        #pragma unroll
        for (int o = 16; o > 0; o >>= 1) ns += __shfl_xor_sync(0xffffffff, ns, o);
        if (lane == 0) {
            const float r = 1.f / fmaxf(sqrtf(ns), 1e-12f);
            iv[j] = r;
            invn[bId * Ld + t] = r;
        }
    }
    __syncthreads();

    {
        const int ty = tid >> 4, tx = tid & 15;
        float acc[4][4];
        #pragma unroll
        for (int i = 0; i < 4; i++)
            #pragma unroll
            for (int j = 0; j < 4; j++) acc[i][j] = 0.f;
        #pragma unroll 4
        for (int kk = 0; kk < 256; kk++) {
            float av[4], bv[4];
            #pragma unroll
            for (int i = 0; i < 4; i++) av[i] = Ks[(4 * ty + i) * PSTR + kk];
            #pragma unroll
            for (int j = 0; j < 4; j++) bv[j] = Ks[(4 * tx + j) * PSTR + kk];
            #pragma unroll
            for (int i = 0; i < 4; i++)
                #pragma unroll
                for (int j = 0; j < 4; j++) acc[i][j] += av[i] * bv[j];
        }
        #pragma unroll
        for (int i = 0; i < 4; i++)
            #pragma unroll
            for (int j = 0; j < 4; j++) {
                const int r = 4 * ty + i, c = 4 * tx + j;
                G[r * 65 + c] = CEMA * iv[r] * iv[c] * acc[i][j];
            }
    }
    __syncthreads();

    if (w == 0) {
        const int c = lane;
        float x[32];
        #pragma unroll
        for (int j = 0; j < 32; j++) {
            float sum = (j == c) ? 1.f : 0.f;
            #pragma unroll
            for (int l = 0; l < 32; l++)
                if (l < j) sum -= G[j * 65 + l] * x[l];
            x[j] = sum;
        }
        #pragma unroll
        for (int j = 0; j < 32; j++) Ts[j * 65 + c] = x[j];
    } else if (w == 1) {
        const int c = lane;
        float x[32];
        #pragma unroll
        for (int j = 0; j < 32; j++) {
            float sum = (j == c) ? 1.f : 0.f;
            #pragma unroll
            for (int l = 0; l < 32; l++)
                if (l < j) sum -= G[(32 + j) * 65 + 32 + l] * x[l];
            x[j] = sum;
        }
        #pragma unroll
        for (int j = 0; j < 32; j++) Ts[(32 + j) * 65 + 32 + c] = x[j];
    } else {
        for (int e = tid - 64; e < 1024; e += 192) {
            if (e >= 0) Ts[(e >> 5) * 65 + 32 + (e & 31)] = 0.f;
        }
    }
    __syncthreads();

    #pragma unroll
    for (int q = 0; q < 4; q++) {
        const int e = tid + 256 * q;
        const int r = e >> 5, c = e & 31;
        float s = 0.f;
        #pragma unroll
        for (int l = 0; l < 32; l++)
            s += G[(32 + r) * 65 + l] * Ts[l * 65 + c];
        Us[r * 33 + c] = s;
    }
    __syncthreads();

    #pragma unroll
    for (int q = 0; q < 4; q++) {
        const int e = tid + 256 * q;
        const int r = e >> 5, c = e & 31;
        float s = 0.f;
        #pragma unroll
        for (int l = 0; l < 32; l++)
            s += Ts[(32 + r) * 65 + 32 + l] * Us[l * 33 + c];
        Ts[(32 + r) * 65 + c] = -s;
    }
    __syncthreads();

    float* Tg = Tout + ((long)(bId * NCH + cId) << 12);
    #pragma unroll
    for (int q = 0; q < 16; q++) {
        const int e = tid + 256 * q;
        Tg[e] = Ts[(e >> 6) * 65 + (e & 63)];
    }
}

// ---------------------------------------------------------------------------
// Chunked backward scan + fused readout projection (rp).
// ---------------------------------------------------------------------------
__global__ __launch_bounds__(256) void scan_kernel(
    const float* __restrict__ X, const float* __restrict__ He,
    const float* __restrict__ invn, const float* __restrict__ Tin,
    const float* __restrict__ gamma, const float* __restrict__ beta,
    const float* __restrict__ Wrp, const float* __restrict__ brp,
    float* __restrict__ mmout)
{
    extern __shared__ float sh[];
    float* Kb   = sh;                     // [2][64][KSTR]
    float* Tb   = Kb + 2 * 64 * KSTR;     // [2][64][TSTR]
    float* ivb  = Tb + 2 * 64 * TSTR;     // [2][64]
    float* vsm  = ivb + 128;              // [256]
    float* bsm  = vsm + 256;              // [64]
    float* csm  = bsm + 64;               // [64]
    float* cnsm = csm + 64;               // [64]

    const int bId = blockIdx.x;
    const int tid = threadIdx.x;
    const int w = tid >> 5, lane = tid & 31;
    const float* Hb = He + (long)bId * Ld * Hd;
    const float* In = invn + bId * Ld;
    const float* Tc = Tin + ((long)bId * NCH << 12);

    auto issue = [&](int buf, int c) {
        float* K = Kb + buf * 64 * KSTR;
        #pragma unroll
        for (int q = 0; q < 16; q++) {
            const int idx = tid + 256 * q;
            const int j = idx >> 6, c4 = idx & 63;
            const int t = 510 - (64 * c + j);
            float* dst = K + j * KSTR + c4 * 4;
            if (t >= 0) cp16(dst, Hb + (long)t * Hd + c4 * 4);
            else        *(float4*)dst = make_float4(0.f, 0.f, 0.f, 0.f);
        }
        #pragma unroll
        for (int q = 0; q < 4; q++) {
            const int idx = tid + 256 * q;
            const int r = idx >> 4, c4 = idx & 15;
            cp16(Tb + buf * 64 * TSTR + r * TSTR + c4 * 4,
                 Tc + ((long)c << 12) + r * 64 + c4 * 4);
        }
        if (tid < 64) {
            const int t = 510 - (64 * c + tid);
            ivb[buf * 64 + tid] = (t >= 0) ? In[t] : 0.f;
        }
    };

    issue(0, 0);
    CP_COMMIT();
    {
        const float xq = X[((long)bId * Ld + 511) * Hd + tid];
        float s = xq;
        #pragma unroll
        for (int o = 16; o > 0; o >>= 1) s += __shfl_xor_sync(0xffffffff, s, o);
        if (lane == 0) bsm[w] = s;
        __syncthreads();
        float mu = 0.f;
        #pragma unroll
        for (int e = 0; e < 8; e++) mu += bsm[e];
        mu *= (1.f / Hd);
        const float d = xq - mu;
        float ss = d * d;
        #pragma unroll
        for (int o = 16; o > 0; o >>= 1) ss += __shfl_xor_sync(0xffffffff, ss, o);
        if (lane == 0) csm[w] = ss;
        __syncthreads();
        float var = 0.f;
        #pragma unroll
        for (int e = 0; e < 8; e++) var += csm[e];
        const float rstd = rsqrtf(var * (1.f / Hd) + 1e-5f);
        vsm[tid] = d * rstd * gamma[tid] + beta[tid];
    }
    float mi = 0.f;
    CP_WAIT(0);
    __syncthreads();

    const int jrow = tid >> 2, sub = tid & 3;
    int buf = 0;
    #pragma unroll 1
    for (int c = 0; c < NCH; c++) {
        if (c + 1 < NCH) { issue(buf ^ 1, c + 1); CP_COMMIT(); }

        float* K  = Kb + buf * 64 * KSTR;
        float* T  = Tb + buf * 64 * TSTR;
        float* iv = ivb + buf * 64;

        {
            const float* Kr = K + jrow * KSTR;
            float p0 = 0.f, p1 = 0.f;
            #pragma unroll
            for (int i = 0; i < 64; i += 2) {
                p0 += Kr[sub + 4 * i]       * vsm[sub + 4 * i];
                p1 += Kr[sub + 4 * (i + 1)] * vsm[sub + 4 * (i + 1)];
            }
            float s = p0 + p1;
            s += __shfl_xor_sync(0xffffffff, s, 1);
            s += __shfl_xor_sync(0xffffffff, s, 2);
            if (sub == 0) bsm[jrow] = s * iv[jrow];
        }
        __syncthreads();

        {
            const float* Tr = T + jrow * TSTR + sub * 16;
            const float* br = bsm + sub * 16;
            float t0 = 0.f, t1 = 0.f;
            #pragma unroll
            for (int q = 0; q < 16; q += 2) {
                t0 += Tr[q]     * br[q];
                t1 += Tr[q + 1] * br[q + 1];
            }
            float t = t0 + t1;
            t += __shfl_xor_sync(0xffffffff, t, 1);
            t += __shfl_xor_sync(0xffffffff, t, 2);
            if (sub == 0) {
                const float cs = CEMA * t;
                csm[jrow]  = cs;
                cnsm[jrow] = cs * iv[jrow];
            }
        }
        __syncthreads();

        {
            float vi = vsm[tid];
            float dm0 = 0.f, dm1 = 0.f, dv0 = 0.f, dv1 = 0.f;
            #pragma unroll
            for (int j = 0; j < 64; j += 2) {
                const float k0 = K[j * KSTR + tid];
                const float k1 = K[(j + 1) * KSTR + tid];
                dm0 += csm[j] * k0;     dv0 += cnsm[j] * k0;
                dm1 += csm[j + 1] * k1; dv1 += cnsm[j + 1] * k1;
            }
            mi += dm0 + dm1;
            vsm[tid] = vi - (dv0 + dv1);
        }
        if (c + 1 < NCH) CP_WAIT(0);
        __syncthreads();
        buf ^= 1;
    }

    // fused rp: mm = m @ Wrp + brp
    vsm[tid] = mi;
    __syncthreads();
    float acc = brp[tid];
    #pragma unroll 8
    for (int k = 0; k < Hd; k++) acc += vsm[k] * Wrp[k * Hd + tid];
    mmout[bId * Hd + tid] = acc;
}

// ---------------------------------------------------------------------------
// out[8,32000] = mm @ Wout + bout
// ---------------------------------------------------------------------------
__global__ __launch_bounds__(128) void out_kernel(
    const float* __restrict__ mm, const float* __restrict__ Wout,
    const float* __restrict__ bout, float* __restrict__ out)
{
    __shared__ float ms[Bq][Hd];
    int tid = threadIdx.x;
    #pragma unroll
    for (int i = tid; i < Bq * Hd; i += 128) ms[i >> 8][i & 255] = mm[i];
    __syncthreads();

    int col = blockIdx.x * 128 + tid;
    float acc[Bq];
    float bo = bout[col];
    #pragma unroll
    for (int b = 0; b < Bq; b++) acc[b] = bo;

    #pragma unroll 4
    for (int k = 0; k < Hd; k++) {
        float w = Wout[(long)k * Vv + col];
        #pragma unroll
        for (int b = 0; b < Bq; b++) acc[b] += ms[b][k] * w;
    }
    #pragma unroll
    for (int b = 0; b < Bq; b++) out[(long)b * Vv + col] = acc[b];
}

// ---------------------------------------------------------------------------
extern "C" void kernel_launch(void* const* d_in, const int* in_sizes, int n_in,
                              void* d_out, int out_size)
{
    const int*   seq   = (const int*)  d_in[0];
    const float* embed = (const float*)d_in[1];
    const float* W1    = (const float*)d_in[2];
    const float* b1    = (const float*)d_in[3];
    const float* W2    = (const float*)d_in[4];
    const float* b2    = (const float*)d_in[5];
    const float* gamma = (const float*)d_in[6];
    const float* beta  = (const float*)d_in[7];
    const float* Wrp   = (const float*)d_in[8];
    const float* brp   = (const float*)d_in[9];
    const float* Wout  = (const float*)d_in[10];
    const float* bout  = (const float*)d_in[11];
    float* out = (float*)d_out;

    bf16 *A1h, *A1l, *W1h, *W1l, *W2h, *W2l, *t1h, *t1l;
    float *x, *he, *invn, *Tm, *mm;
    cudaGetSymbolAddress((void**)&A1h, g_A1h);
    cudaGetSymbolAddress((void**)&A1l, g_A1l);
    cudaGetSymbolAddress((void**)&W1h, g_W1h);
    cudaGetSymbolAddress((void**)&W1l, g_W1l);
    cudaGetSymbolAddress((void**)&W2h, g_W2h);
    cudaGetSymbolAddress((void**)&W2l, g_W2l);
    cudaGetSymbolAddress((void**)&t1h, g_t1h);
    cudaGetSymbolAddress((void**)&t1l, g_t1l);
    cudaGetSymbolAddress((void**)&x,    g_x);
    cudaGetSymbolAddress((void**)&he,   g_he);
    cudaGetSymbolAddress((void**)&invn, g_in);
    cudaGetSymbolAddress((void**)&Tm,   g_T);
    cudaGetSymbolAddress((void**)&mm,   g_mm);

    const int gemmSmem = (2 * 2 * 64 * 40 + 2 * 2 * 128 * 40) * 2;   // 61440
    const int prepSmem = (64 * PSTR + 64 * 65 + 64 * 65 + 32 * 33
                          + 256 + 256 + 64) * 4;
    const int scanSmem = (2 * 64 * KSTR + 2 * 64 * TSTR + 128
                          + 256 + 64 * 3) * 4;
    cudaFuncSetAttribute(mma_gemm_kernel<1>,
        cudaFuncAttributeMaxDynamicSharedMemorySize, gemmSmem);
    cudaFuncSetAttribute(mma_gemm_kernel<2>,
        cudaFuncAttributeMaxDynamicSharedMemorySize, gemmSmem);
    cudaFuncSetAttribute(prep_kernel,
        cudaFuncAttributeMaxDynamicSharedMemorySize, prepSmem);
    cudaFuncSetAttribute(scan_kernel,
        cudaFuncAttributeMaxDynamicSharedMemorySize, scanSmem);

    // 0) gather/split A1, transpose/split W1 & W2 (one kernel)
    conv_kernel<<<768, 256>>>(seq, embed, W1, W2,
                              A1h, A1l, W1h, W1l, W2h, W2l);

    // 1) t1 = relu(A1 @ W1 + b1) -> bf16 hi/lo    [4096,512]
    mma_gemm_kernel<1><<<dim3(512 / 128, NTOK / 64), 256, gemmSmem>>>(
        A1h, A1l, W1h, W1l, b1, nullptr, t1h, t1l,
        NTOK, 512, Hd, seq, embed);

    // 2) x = t1 @ W2 + b2 + embed[seq]            [4096,256]
    mma_gemm_kernel<2><<<dim3(Hd / 128, NTOK / 64), 256, gemmSmem>>>(
        t1h, t1l, W2h, W2l, b2, x, nullptr, nullptr,
        NTOK, Hd, 512, seq, embed);

    // 3) LN + Gram + chunk inverse T
    prep_kernel<<<Bq * NCH, 256, prepSmem>>>(x, gamma, beta, he, invn, Tm);

    // 4) chunked backward scan -> mm (rp fused)
    scan_kernel<<<Bq, 256, scanSmem>>>(x, he, invn, Tm, gamma, beta,
                                       Wrp, brp, mm);

    // 5) out = mm @ Wout + bout
    out_kernel<<<Vv / 128, 128>>>(mm, Wout, bout, out);
}

// round 8
// speedup vs baseline: 2.4513x; 1.0528x over previous
#include <cuda_runtime.h>
#include <cuda_bf16.h>

// Problem constants
#define Hd   256
#define Ld   512
#define Bq   8
#define NTOK 4096            // B*L
#define Vv   32000
#define CEMA 0.05f           // 1 - alpha
#define CSZ  64              // chunk size
#define NCH  8               // chunks per batch
#define KSTR 260             // K-tile smem row stride (scan, fp32 words)
#define TSTR 68              // T smem row stride
#define STRB 264             // prep bf16 key row stride (528B: ldsm conflict-free)

typedef __nv_bfloat16 bf16;

// Scratch (device globals)
__device__ bf16  g_A1h[NTOK * Hd],  g_A1l[NTOK * Hd];
__device__ bf16  g_W1h[512 * Hd],   g_W1l[512 * Hd];
__device__ bf16  g_W2h[Hd * 512],   g_W2l[Hd * 512];
__device__ bf16  g_t1h[NTOK * 512], g_t1l[NTOK * 512];
__device__ float g_x [NTOK * Hd];
__device__ float g_he[NTOK * Hd];
__device__ float g_in[NTOK];
__device__ float g_T [Bq * NCH * CSZ * CSZ];
__device__ float g_mm[Bq * Hd];

// cp.async helpers
__device__ __forceinline__ void cp16(void* dst, const void* src) {
    unsigned d = (unsigned)__cvta_generic_to_shared(dst);
    asm volatile("cp.async.ca.shared.global [%0], [%1], 16;\n" :: "r"(d), "l"(src));
}
#define CP_COMMIT() asm volatile("cp.async.commit_group;\n" ::: "memory")
#define CP_WAIT(n)  asm volatile("cp.async.wait_group %0;\n" :: "n"(n) : "memory")

__device__ __forceinline__ void mma_bf16(float* d, const unsigned* a, const unsigned* b) {
    asm volatile(
        "mma.sync.aligned.m16n8k16.row.col.f32.bf16.bf16.f32 "
        "{%0,%1,%2,%3}, {%4,%5,%6,%7}, {%8,%9}, {%0,%1,%2,%3};"
        : "+f"(d[0]), "+f"(d[1]), "+f"(d[2]), "+f"(d[3])
        : "r"(a[0]), "r"(a[1]), "r"(a[2]), "r"(a[3]), "r"(b[0]), "r"(b[1]));
}

__device__ __forceinline__ void ldsm4(unsigned* r, unsigned addr) {
    asm volatile("ldmatrix.sync.aligned.m8n8.x4.shared.b16 {%0,%1,%2,%3}, [%4];"
        : "=r"(r[0]), "=r"(r[1]), "=r"(r[2]), "=r"(r[3]) : "r"(addr));
}

__device__ __forceinline__ void split2(float v, bf16& h, bf16& l) {
    h = __float2bfloat16_rn(v);
    l = __float2bfloat16_rn(v - __bfloat162float(h));
}

// ---------------------------------------------------------------------------
// Combined conversion kernel (unchanged from R7)
// ---------------------------------------------------------------------------
__global__ __launch_bounds__(256) void conv_kernel(
    const int* __restrict__ seq, const float* __restrict__ embed,
    const float* __restrict__ W1, const float* __restrict__ W2,
    bf16* __restrict__ Ah, bf16* __restrict__ Al,
    bf16* __restrict__ W1h, bf16* __restrict__ W1l,
    bf16* __restrict__ W2h, bf16* __restrict__ W2l)
{
    __shared__ float tile[32][33];
    const int b = blockIdx.x;
    if (b < 512) {
        const int c = threadIdx.x;
        #pragma unroll
        for (int i = 0; i < 8; i++) {
            const int r = b * 8 + i;
            const float v = embed[(long)seq[r] * Hd + c];
            bf16 h, l; split2(v, h, l);
            Ah[(long)r * Hd + c] = h;
            Al[(long)r * Hd + c] = l;
        }
        return;
    }
    const float* W; bf16 *Wh, *Wl; int K, N, n0, k0;
    if (b < 640) {
        const int p = b - 512;
        W = W1; Wh = W1h; Wl = W1l; K = Hd; N = 512;
        n0 = (p & 15) * 32; k0 = (p >> 4) * 32;
    } else {
        const int p = b - 640;
        W = W2; Wh = W2h; Wl = W2l; K = 512; N = Hd;
        n0 = (p & 7) * 32; k0 = (p >> 3) * 32;
    }
    const int tx = threadIdx.x & 31, ty = threadIdx.x >> 5;
    #pragma unroll
    for (int i = 0; i < 4; i++)
        tile[ty + 8 * i][tx] = W[(long)(k0 + ty + 8 * i) * N + n0 + tx];
    __syncthreads();
    #pragma unroll
    for (int i = 0; i < 4; i++) {
        const int row = ty + 8 * i;
        const float v = tile[tx][row];
        bf16 h, l; split2(v, h, l);
        Wh[(long)(n0 + row) * K + k0 + tx] = h;
        Wl[(long)(n0 + row) * K + k0 + tx] = l;
    }
}

// ---------------------------------------------------------------------------
// Tensor-core GEMM, bf16x3, ldmatrix (unchanged from R7)
// ---------------------------------------------------------------------------
template<int MODE>
__global__ __launch_bounds__(256, 2) void mma_gemm_kernel(
    const bf16* __restrict__ Agh, const bf16* __restrict__ Agl,
    const bf16* __restrict__ Bgh, const bf16* __restrict__ Bgl,
    const float* __restrict__ bias,
    float* __restrict__ Cf, bf16* __restrict__ Ch, bf16* __restrict__ Cl,
    int M, int N, int K,
    const int* __restrict__ seq, const float* __restrict__ embed)
{
    constexpr int BK = 32, STR = 40;
    extern __shared__ bf16 sm[];
    bf16* sA = sm;
    bf16* sB = sm + 2 * 2 * 64 * STR;

    const int tid = threadIdx.x;
    const int lane = tid & 31;
    const int wid = tid >> 5;
    const int warpM = wid & 1, warpN = wid >> 1;
    const int rowBase = blockIdx.y * 64;
    const int colBase = blockIdx.x * 128;

    auto issue = [&](int buf, int s) {
        const int k0 = s * BK;
        {
            const int r = tid >> 2, c = (tid & 3) * 8;
            const long goff = (long)(rowBase + r) * K + k0 + c;
            cp16(sA + (buf * 2 + 0) * 64 * STR + r * STR + c, Agh + goff);
            cp16(sA + (buf * 2 + 1) * 64 * STR + r * STR + c, Agl + goff);
        }
        #pragma unroll
        for (int q = 0; q < 2; q++) {
            const int idx = tid + 256 * q;
            const int n = idx >> 2, c = (idx & 3) * 8;
            const long goff = (long)(colBase + n) * K + k0 + c;
            cp16(sB + (buf * 2 + 0) * 128 * STR + n * STR + c, Bgh + goff);
            cp16(sB + (buf * 2 + 1) * 128 * STR + n * STR + c, Bgl + goff);
        }
    };

    float d[2][4][4];
    #pragma unroll
    for (int mt = 0; mt < 2; mt++)
        #pragma unroll
        for (int nt = 0; nt < 4; nt++)
            #pragma unroll
            for (int e = 0; e < 4; e++) d[mt][nt][e] = 0.f;

    const int nst = K / BK;
    issue(0, 0);
    CP_COMMIT();

    const unsigned smemBase = (unsigned)__cvta_generic_to_shared(sm);
    const int lane8 = lane & 7, ls = lane >> 3;
    const int aRow = warpM * 32 + lane8 + ((ls & 1) << 3);
    const int aCol = (ls & 2) << 2;
    const int bRow = warpN * 32 + lane8 + ((ls & 2) << 2);
    const int bCol = (ls & 1) << 3;
    const unsigned sBbase = smemBase + 2u * (2 * 2 * 64 * STR);

    for (int s = 0; s < nst; s++) {
        const int buf = s & 1;
        if (s + 1 < nst) { issue(buf ^ 1, s + 1); CP_COMMIT(); CP_WAIT(1); }
        else             { CP_WAIT(0); }
        __syncthreads();

        const unsigned aBuf = smemBase + 2u * (buf * 2 * 64 * STR);
        const unsigned bBuf = sBbase   + 2u * (buf * 2 * 128 * STR);

        #pragma unroll
        for (int h = 0; h < 2; h++) {
            const int hk = h * 16;
            unsigned ah[2][4], al[2][4], bh[2][4], bl[2][4];
            #pragma unroll
            for (int mt = 0; mt < 2; mt++) {
                const unsigned off = 2u * ((aRow + mt * 16) * STR + hk + aCol);
                ldsm4(ah[mt], aBuf + off);
                ldsm4(al[mt], aBuf + 2u * (64 * STR) + off);
            }
            #pragma unroll
            for (int p = 0; p < 2; p++) {
                const unsigned off = 2u * ((bRow + p * 16) * STR + hk + bCol);
                ldsm4(bh[p], bBuf + off);
                ldsm4(bl[p], bBuf + 2u * (128 * STR) + off);
            }
            #pragma unroll
            for (int mt = 0; mt < 2; mt++)
                #pragma unroll
                for (int nt = 0; nt < 4; nt++) {
                    const int p = nt >> 1, o = (nt & 1) * 2;
                    mma_bf16(d[mt][nt], ah[mt], &bh[p][o]);
                    mma_bf16(d[mt][nt], ah[mt], &bl[p][o]);
                    mma_bf16(d[mt][nt], al[mt], &bh[p][o]);
                }
        }
        __syncthreads();
    }

    const int lr = lane >> 2;
    const int lk = 2 * (lane & 3);
    #pragma unroll
    for (int mt = 0; mt < 2; mt++) {
        #pragma unroll
        for (int nt = 0; nt < 4; nt++) {
            const int cc = colBase + warpN * 32 + nt * 8 + lk;
            const float b0 = bias[cc], b1 = bias[cc + 1];
            #pragma unroll
            for (int half = 0; half < 2; half++) {
                const int r = rowBase + warpM * 32 + mt * 16 + lr + half * 8;
                float v0 = d[mt][nt][half * 2 + 0] + b0;
                float v1 = d[mt][nt][half * 2 + 1] + b1;
                if (MODE == 1) {
                    v0 = fmaxf(v0, 0.f); v1 = fmaxf(v1, 0.f);
                    bf16 h0, l0, h1, l1;
                    split2(v0, h0, l0); split2(v1, h1, l1);
                    const long off = (long)r * N + cc;
                    *(__nv_bfloat162*)(Ch + off) = __halves2bfloat162(h0, h1);
                    *(__nv_bfloat162*)(Cl + off) = __halves2bfloat162(l0, l1);
                } else {
                    const float* erow = embed + (long)seq[r] * Hd + cc;
                    v0 += erow[0]; v1 += erow[1];
                    *(float2*)(Cf + (long)r * N + cc) = make_float2(v0, v1);
                }
            }
        }
    }
}

// ---------------------------------------------------------------------------
// Prep kernel v2: LN -> bf16 hi/lo keys in smem; Gram via tensor cores
// (Kh*Kh^T + Kh*Kl^T + Kl*Kh^T); T = (I + strict_lower(c*iv*G*iv))^-1.
// 64 blocks x 256 threads.
// ---------------------------------------------------------------------------
__global__ __launch_bounds__(256) void prep_kernel(
    const float* __restrict__ X, const float* __restrict__ gamma,
    const float* __restrict__ beta, float* __restrict__ He,
    float* __restrict__ invn, float* __restrict__ Tout)
{
    extern __shared__ char shc[];
    bf16*  Kh = (bf16*)shc;                        // [64][STRB]
    bf16*  Kl = Kh + 64 * STRB;                    // [64][STRB]
    float* G  = (float*)(Kl + 64 * STRB);          // [64][65]
    float* Ts = G  + 64 * 65;                      // [64][65]
    float* Us = Ts + 64 * 65;                      // [32][33]
    float* gm = Us + 32 * 33;                      // [256]
    float* bt = gm + 256;                          // [256]
    float* iv = bt + 256;                          // [64]

    const int bId = blockIdx.x >> 3;
    const int cId = blockIdx.x & 7;
    const int tid = threadIdx.x;
    const int w = tid >> 5, lane = tid & 31;

    gm[tid] = gamma[tid];
    bt[tid] = beta[tid];
    __syncthreads();

    // --- LayerNorm 8 rows per warp; emit bf16 hi/lo keys + He + invn
    #pragma unroll
    for (int it = 0; it < 8; it++) {
        const int j = w * 8 + it;
        const int t = 510 - (64 * cId + j);
        if (t < 0) {
            #pragma unroll
            for (int e = 0; e < 8; e++) {
                Kh[j * STRB + lane + 32 * e] = __float2bfloat16(0.f);
                Kl[j * STRB + lane + 32 * e] = __float2bfloat16(0.f);
            }
            if (lane == 0) iv[j] = 0.f;
            continue;
        }
        const float* x = X + ((long)bId * Ld + t) * Hd;
        float v[8], s = 0.f;
        #pragma unroll
        for (int e = 0; e < 8; e++) { v[e] = x[lane + 32 * e]; s += v[e]; }
        #pragma unroll
        for (int o = 16; o > 0; o >>= 1) s += __shfl_xor_sync(0xffffffff, s, o);
        const float mu = s * (1.f / Hd);
        float ss = 0.f;
        #pragma unroll
        for (int e = 0; e < 8; e++) { float dd = v[e] - mu; ss += dd * dd; }
        #pragma unroll
        for (int o = 16; o > 0; o >>= 1) ss += __shfl_xor_sync(0xffffffff, ss, o);
        const float rstd = rsqrtf(ss * (1.f / Hd) + 1e-5f);
        float ns = 0.f;
        float* herow = He + ((long)bId * Ld + t) * Hd;
        #pragma unroll
        for (int e = 0; e < 8; e++) {
            const int c = lane + 32 * e;
            const float o = (v[e] - mu) * rstd * gm[c] + bt[c];
            bf16 h, l; split2(o, h, l);
            Kh[j * STRB + c] = h;
            Kl[j * STRB + c] = l;
            herow[c] = o;
            ns += o * o;
        }
        #pragma unroll
        for (int o = 16; o > 0; o >>= 1) ns += __shfl_xor_sync(0xffffffff, ns, o);
        if (lane == 0) {
            const float r = 1.f / fmaxf(sqrtf(ns), 1e-12f);
            iv[j] = r;
            invn[bId * Ld + t] = r;
        }
    }
    __syncthreads();

    // --- Gram via tensor cores: warp w owns rows (w&3)*16, cols (w>>2)*32
    {
        const int warpM = w & 3, warpN = w >> 2;
        const unsigned khB = (unsigned)__cvta_generic_to_shared(Kh);
        const unsigned klB = (unsigned)__cvta_generic_to_shared(Kl);
        const int lane8 = lane & 7, ls = lane >> 3;
        const int aRow = warpM * 16 + lane8 + ((ls & 1) << 3);
        const int aCol = (ls & 2) << 2;
        const int bRow = warpN * 32 + lane8 + ((ls & 2) << 2);
        const int bCol = (ls & 1) << 3;

        float d[4][4];
        #pragma unroll
        for (int nt = 0; nt < 4; nt++)
            #pragma unroll
            for (int e = 0; e < 4; e++) d[nt][e] = 0.f;

        #pragma unroll
        for (int s = 0; s < 16; s++) {
            const int hk = s * 16;
            unsigned ah[4], al[4], bh[2][4], bl[2][4];
            {
                const unsigned off = 2u * (aRow * STRB + hk + aCol);
                ldsm4(ah, khB + off);
                ldsm4(al, klB + off);
            }
            #pragma unroll
            for (int p = 0; p < 2; p++) {
                const unsigned off = 2u * ((bRow + p * 16) * STRB + hk + bCol);
                ldsm4(bh[p], khB + off);
                ldsm4(bl[p], klB + off);
            }
            #pragma unroll
            for (int nt = 0; nt < 4; nt++) {
                const int p = nt >> 1, o = (nt & 1) * 2;
                mma_bf16(d[nt], ah, &bh[p][o]);
                mma_bf16(d[nt], ah, &bl[p][o]);
                mma_bf16(d[nt], al, &bh[p][o]);
            }
        }

        // scale + store G
        const int lr = lane >> 2, lk = 2 * (lane & 3);
        #pragma unroll
        for (int nt = 0; nt < 4; nt++) {
            const int c = warpN * 32 + nt * 8 + lk;
            #pragma unroll
            for (int half = 0; half < 2; half++) {
                const int r = warpM * 16 + lr + half * 8;
                const float sc = CEMA * iv[r];
                G[r * 65 + c]     = sc * iv[c]     * d[nt][half * 2 + 0];
                G[r * 65 + c + 1] = sc * iv[c + 1] * d[nt][half * 2 + 1];
            }
        }
    }
    __syncthreads();

    // --- T = (I + strict_lower(G))^-1 via 2x2 block inversion
    if (w == 0) {
        const int c = lane;
        float x[32];
        #pragma unroll
        for (int j = 0; j < 32; j++) {
            float sum = (j == c) ? 1.f : 0.f;
            #pragma unroll
            for (int l = 0; l < 32; l++)
                if (l < j) sum -= G[j * 65 + l] * x[l];
            x[j] = sum;
        }
        #pragma unroll
        for (int j = 0; j < 32; j++) Ts[j * 65 + c] = x[j];
    } else if (w == 1) {
        const int c = lane;
        float x[32];
        #pragma unroll
        for (int j = 0; j < 32; j++) {
            float sum = (j == c) ? 1.f : 0.f;
            #pragma unroll
            for (int l = 0; l < 32; l++)
                if (l < j) sum -= G[(32 + j) * 65 + 32 + l] * x[l];
            x[j] = sum;
        }
        #pragma unroll
        for (int j = 0; j < 32; j++) Ts[(32 + j) * 65 + 32 + c] = x[j];
    } else {
        for (int e = tid - 64; e < 1024; e += 192) {
            if (e >= 0) Ts[(e >> 5) * 65 + 32 + (e & 31)] = 0.f;
        }
    }
    __syncthreads();

    #pragma unroll
    for (int q = 0; q < 4; q++) {
        const int e = tid + 256 * q;
        const int r = e >> 5, c = e & 31;
        float s = 0.f;
        #pragma unroll
        for (int l = 0; l < 32; l++)
            s += G[(32 + r) * 65 + l] * Ts[l * 65 + c];
        Us[r * 33 + c] = s;
    }
    __syncthreads();

    #pragma unroll
    for (int q = 0; q < 4; q++) {
        const int e = tid + 256 * q;
        const int r = e >> 5, c = e & 31;
        float s = 0.f;
        #pragma unroll
        for (int l = 0; l < 32; l++)
            s += Ts[(32 + r) * 65 + 32 + l] * Us[l * 33 + c];
        Ts[(32 + r) * 65 + c] = -s;
    }
    __syncthreads();

    float* Tg = Tout + ((long)(bId * NCH + cId) << 12);
    #pragma unroll
    for (int q = 0; q < 16; q++) {
        const int e = tid + 256 * q;
        Tg[e] = Ts[(e >> 6) * 65 + (e & 63)];
    }
}

// ---------------------------------------------------------------------------
// Chunked backward scan + fused rp. Phase A/C vectorized (float4).
// ---------------------------------------------------------------------------
__global__ __launch_bounds__(256) void scan_kernel(
    const float* __restrict__ X, const float* __restrict__ He,
    const float* __restrict__ invn, const float* __restrict__ Tin,
    const float* __restrict__ gamma, const float* __restrict__ beta,
    const float* __restrict__ Wrp, const float* __restrict__ brp,
    float* __restrict__ mmout)
{
    extern __shared__ float sh[];
    float* Kb   = sh;                     // [2][64][KSTR]
    float* Tb   = Kb + 2 * 64 * KSTR;     // [2][64][TSTR]
    float* ivb  = Tb + 2 * 64 * TSTR;     // [2][64]
    float* vsm  = ivb + 128;              // [256]
    float* bsm  = vsm + 256;              // [64]
    float* csm  = bsm + 64;               // [64]
    float* cnsm = csm + 64;               // [64]

    const int bId = blockIdx.x;
    const int tid = threadIdx.x;
    const int w = tid >> 5, lane = tid & 31;
    const float* Hb = He + (long)bId * Ld * Hd;
    const float* In = invn + bId * Ld;
    const float* Tc = Tin + ((long)bId * NCH << 12);

    auto issue = [&](int buf, int c) {
        float* K = Kb + buf * 64 * KSTR;
        #pragma unroll
        for (int q = 0; q < 16; q++) {
            const int idx = tid + 256 * q;
            const int j = idx >> 6, c4 = idx & 63;
            const int t = 510 - (64 * c + j);
            float* dst = K + j * KSTR + c4 * 4;
            if (t >= 0) cp16(dst, Hb + (long)t * Hd + c4 * 4);
            else        *(float4*)dst = make_float4(0.f, 0.f, 0.f, 0.f);
        }
        #pragma unroll
        for (int q = 0; q < 4; q++) {
            const int idx = tid + 256 * q;
            const int r = idx >> 4, c4 = idx & 15;
            cp16(Tb + buf * 64 * TSTR + r * TSTR + c4 * 4,
                 Tc + ((long)c << 12) + r * 64 + c4 * 4);
        }
        if (tid < 64) {
            const int t = 510 - (64 * c + tid);
            ivb[buf * 64 + tid] = (t >= 0) ? In[t] : 0.f;
        }
    };

    issue(0, 0);
    CP_COMMIT();
    {
        const float xq = X[((long)bId * Ld + 511) * Hd + tid];
        float s = xq;
        #pragma unroll
        for (int o = 16; o > 0; o >>= 1) s += __shfl_xor_sync(0xffffffff, s, o);
        if (lane == 0) bsm[w] = s;
        __syncthreads();
        float mu = 0.f;
        #pragma unroll
        for (int e = 0; e < 8; e++) mu += bsm[e];
        mu *= (1.f / Hd);
        const float d = xq - mu;
        float ss = d * d;
        #pragma unroll
        for (int o = 16; o > 0; o >>= 1) ss += __shfl_xor_sync(0xffffffff, ss, o);
        if (lane == 0) csm[w] = ss;
        __syncthreads();
        float var = 0.f;
        #pragma unroll
        for (int e = 0; e < 8; e++) var += csm[e];
        const float rstd = rsqrtf(var * (1.f / Hd) + 1e-5f);
        vsm[tid] = d * rstd * gamma[tid] + beta[tid];
    }
    float mi = 0.f;
    CP_WAIT(0);
    __syncthreads();

    const int jrow = tid >> 2, sub = tid & 3;
    int buf = 0;
    #pragma unroll 1
    for (int c = 0; c < NCH; c++) {
        if (c + 1 < NCH) { issue(buf ^ 1, c + 1); CP_COMMIT(); }

        float* K  = Kb + buf * 64 * KSTR;
        float* T  = Tb + buf * 64 * TSTR;
        float* iv = ivb + buf * 64;

        // phase A: b_j = iv_j * (k_j . v), float4 loads
        {
            const float4* Kr4 = (const float4*)(K + jrow * KSTR);
            const float4* v4  = (const float4*)vsm;
            float p0 = 0.f, p1 = 0.f;
            #pragma unroll
            for (int i = 0; i < 16; i += 2) {
                float4 a0 = Kr4[sub + 4 * i],       b0 = v4[sub + 4 * i];
                float4 a1 = Kr4[sub + 4 * (i + 1)], b1 = v4[sub + 4 * (i + 1)];
                p0 += a0.x * b0.x + a0.y * b0.y + a0.z * b0.z + a0.w * b0.w;
                p1 += a1.x * b1.x + a1.y * b1.y + a1.z * b1.z + a1.w * b1.w;
            }
            float s = p0 + p1;
            s += __shfl_xor_sync(0xffffffff, s, 1);
            s += __shfl_xor_sync(0xffffffff, s, 2);
            if (sub == 0) bsm[jrow] = s * iv[jrow];
        }
        __syncthreads();

        // phase B: s_j = T[j] . b
        {
            const float* Tr = T + jrow * TSTR + sub * 16;
            const float* br = bsm + sub * 16;
            float t0 = 0.f, t1 = 0.f;
            #pragma unroll
            for (int q = 0; q < 16; q += 2) {
                t0 += Tr[q]     * br[q];
                t1 += Tr[q + 1] * br[q + 1];
            }
            float t = t0 + t1;
            t += __shfl_xor_sync(0xffffffff, t, 1);
            t += __shfl_xor_sync(0xffffffff, t, 2);
            if (sub == 0) {
                const float cs = CEMA * t;
                csm[jrow]  = cs;
                cnsm[jrow] = cs * iv[jrow];
            }
        }
        __syncthreads();

        // phase C: rank-64 update; coefficient loads via float4
        {
            float vi = vsm[tid];
            float dm = 0.f, dv = 0.f;
            #pragma unroll
            for (int jq = 0; jq < 16; jq++) {
                const float4 cs4 = ((const float4*)csm)[jq];
                const float4 cn4 = ((const float4*)cnsm)[jq];
                const float k0 = K[(4 * jq + 0) * KSTR + tid];
                const float k1 = K[(4 * jq + 1) * KSTR + tid];
                const float k2 = K[(4 * jq + 2) * KSTR + tid];
                const float k3 = K[(4 * jq + 3) * KSTR + tid];
                dm += cs4.x * k0 + cs4.y * k1 + cs4.z * k2 + cs4.w * k3;
                dv += cn4.x * k0 + cn4.y * k1 + cn4.z * k2 + cn4.w * k3;
            }
            mi += dm;
            vsm[tid] = vi - dv;
        }
        if (c + 1 < NCH) CP_WAIT(0);
        __syncthreads();
        buf ^= 1;
    }

    // fused rp: mm = m @ Wrp + brp
    vsm[tid] = mi;
    __syncthreads();
    float acc = brp[tid];
    #pragma unroll 8
    for (int k = 0; k < Hd; k++) acc += vsm[k] * Wrp[k * Hd + tid];
    mmout[bId * Hd + tid] = acc;
}

// ---------------------------------------------------------------------------
// out[8,32000] = mm @ Wout + bout
// ---------------------------------------------------------------------------
__global__ __launch_bounds__(128) void out_kernel(
    const float* __restrict__ mm, const float* __restrict__ Wout,
    const float* __restrict__ bout, float* __restrict__ out)
{
    __shared__ float ms[Bq][Hd];
    int tid = threadIdx.x;
    #pragma unroll
    for (int i = tid; i < Bq * Hd; i += 128) ms[i >> 8][i & 255] = mm[i];
    __syncthreads();

    int col = blockIdx.x * 128 + tid;
    float acc[Bq];
    float bo = bout[col];
    #pragma unroll
    for (int b = 0; b < Bq; b++) acc[b] = bo;

    #pragma unroll 4
    for (int k = 0; k < Hd; k++) {
        float w = Wout[(long)k * Vv + col];
        #pragma unroll
        for (int b = 0; b < Bq; b++) acc[b] += ms[b][k] * w;
    }
    #pragma unroll
    for (int b = 0; b < Bq; b++) out[(long)b * Vv + col] = acc[b];
}

// ---------------------------------------------------------------------------
extern "C" void kernel_launch(void* const* d_in, const int* in_sizes, int n_in,
                              void* d_out, int out_size)
{
    const int*   seq   = (const int*)  d_in[0];
    const float* embed = (const float*)d_in[1];
    const float* W1    = (const float*)d_in[2];
    const float* b1    = (const float*)d_in[3];
    const float* W2    = (const float*)d_in[4];
    const float* b2    = (const float*)d_in[5];
    const float* gamma = (const float*)d_in[6];
    const float* beta  = (const float*)d_in[7];
    const float* Wrp   = (const float*)d_in[8];
    const float* brp   = (const float*)d_in[9];
    const float* Wout  = (const float*)d_in[10];
    const float* bout  = (const float*)d_in[11];
    float* out = (float*)d_out;

    bf16 *A1h, *A1l, *W1h, *W1l, *W2h, *W2l, *t1h, *t1l;
    float *x, *he, *invn, *Tm, *mm;
    cudaGetSymbolAddress((void**)&A1h, g_A1h);
    cudaGetSymbolAddress((void**)&A1l, g_A1l);
    cudaGetSymbolAddress((void**)&W1h, g_W1h);
    cudaGetSymbolAddress((void**)&W1l, g_W1l);
    cudaGetSymbolAddress((void**)&W2h, g_W2h);
    cudaGetSymbolAddress((void**)&W2l, g_W2l);
    cudaGetSymbolAddress((void**)&t1h, g_t1h);
    cudaGetSymbolAddress((void**)&t1l, g_t1l);
    cudaGetSymbolAddress((void**)&x,    g_x);
    cudaGetSymbolAddress((void**)&he,   g_he);
    cudaGetSymbolAddress((void**)&invn, g_in);
    cudaGetSymbolAddress((void**)&Tm,   g_T);
    cudaGetSymbolAddress((void**)&mm,   g_mm);

    const int gemmSmem = (2 * 2 * 64 * 40 + 2 * 2 * 128 * 40) * 2;   // 61440
    const int prepSmem = 2 * 64 * STRB * 2
                       + (64 * 65 + 64 * 65 + 32 * 33 + 256 + 256 + 64) * 4;
    const int scanSmem = (2 * 64 * KSTR + 2 * 64 * TSTR + 128
                          + 256 + 64 * 3) * 4;
    cudaFuncSetAttribute(mma_gemm_kernel<1>,
        cudaFuncAttributeMaxDynamicSharedMemorySize, gemmSmem);
    cudaFuncSetAttribute(mma_gemm_kernel<2>,
        cudaFuncAttributeMaxDynamicSharedMemorySize, gemmSmem);
    cudaFuncSetAttribute(prep_kernel,
        cudaFuncAttributeMaxDynamicSharedMemorySize, prepSmem);
    cudaFuncSetAttribute(scan_kernel,
        cudaFuncAttributeMaxDynamicSharedMemorySize, scanSmem);

    // 0) gather/split A1, transpose/split W1 & W2
    conv_kernel<<<768, 256>>>(seq, embed, W1, W2,
                              A1h, A1l, W1h, W1l, W2h, W2l);

    // 1) t1 = relu(A1 @ W1 + b1) -> bf16 hi/lo
    mma_gemm_kernel<1><<<dim3(512 / 128, NTOK / 64), 256, gemmSmem>>>(
        A1h, A1l, W1h, W1l, b1, nullptr, t1h, t1l,
        NTOK, 512, Hd, seq, embed);

    // 2) x = t1 @ W2 + b2 + embed[seq]
    mma_gemm_kernel<2><<<dim3(Hd / 128, NTOK / 64), 256, gemmSmem>>>(
        t1h, t1l, W2h, W2l, b2, x, nullptr, nullptr,
        NTOK, Hd, 512, seq, embed);

    // 3) LN + tensor-core Gram + chunk inverse T
    prep_kernel<<<Bq * NCH, 256, prepSmem>>>(x, gamma, beta, he, invn, Tm);

    // 4) chunked backward scan -> mm (rp fused)
    scan_kernel<<<Bq, 256, scanSmem>>>(x, he, invn, Tm, gamma, beta,
                                       Wrp, brp, mm);

    // 5) out = mm @ Wout + bout
    out_kernel<<<Vv / 128, 128>>>(mm, Wout, bout, out);
}